// round 10
// baseline (speedup 1.0000x reference)
#include <cuda_runtime.h>
#include <cuda_bf16.h>
#include <cuda_fp16.h>
#include <cstdint>

#define MMAX 200704
#define NB 256

typedef __half fh;

// ---------------- scratch (device globals; no allocation allowed) ----------------
__device__ float g_A[(size_t)MMAX * 128];   // h segment-sum accumulator
__device__ float g_B[(size_t)MMAX * 128];   // x segment-sum accumulator
__device__ float g_C[(size_t)MMAX * 256];   // h1 (conv1 out, fp32 for GN2 stats)
__device__ float g_cnt[MMAX];
__device__ float g_part[2 * NB * 256];
__device__ float g_scale[256];
__device__ float g_shift[256];
__device__ __align__(16) fh g_zrow[64];     // safe src for zero-fill cp.async
// fp16 operand planes (single plane each)
__device__ fh g_hd[(size_t)MMAX * 128];
__device__ fh g_xd[(size_t)MMAX * 128];
__device__ fh g_h2[(size_t)MMAX * 256];
// weights: chunked+pre-swizzled layout [tap*NCH+ch][n=256][32] (fp16, 16KB blocks)
__device__ __align__(16) fh g_W1[27 * 256 * 128];
__device__ __align__(16) fh g_W2[27 * 256 * 256];
__device__ __align__(16) fh g_WS[256 * 128];

__device__ __forceinline__ float silu_f(float x) { return x / (1.f + __expf(-x)); }

__device__ __forceinline__ uint32_t smem_u32(const void* p) {
    uint32_t a;
    asm("{ .reg .u64 t; cvta.to.shared.u64 t, %1; cvt.u32.u64 %0, t; }" : "=r"(a) : "l"(p));
    return a;
}
// zero-fill form: src-size=0 -> writes 16 zero bytes, NO global read issued
__device__ __forceinline__ void cp_async16z(uint32_t dst, const void* src, uint32_t srcsz) {
    asm volatile("cp.async.cg.shared.global [%0], [%1], 16, %2;"
                 :: "r"(dst), "l"(src), "r"(srcsz));
}
__device__ __forceinline__ void cp_commit() {
    asm volatile("cp.async.commit_group;" ::: "memory");
}
__device__ __forceinline__ void cp_wait0() { asm volatile("cp.async.wait_group 0;" ::: "memory"); }
__device__ __forceinline__ void cp_wait1() { asm volatile("cp.async.wait_group 1;" ::: "memory"); }
__device__ __forceinline__ void cp_wait2() { asm volatile("cp.async.wait_group 2;" ::: "memory"); }
// bulk g2s copy completing on an mbarrier (sm_90 base feature)
__device__ __forceinline__ void cp_bulk_g2s(uint32_t dst, const void* src, uint32_t bytes,
                                            uint32_t mbar) {
    asm volatile(
        "cp.async.bulk.shared::cta.global.mbarrier::complete_tx::bytes [%0], [%1], %2, [%3];"
        :: "r"(dst), "l"(src), "r"(bytes), "r"(mbar) : "memory");
}
#define MBARRIER_INIT(addr, cnt) \
    asm volatile("mbarrier.init.shared.b64 [%0], %1;" :: "r"(addr), "r"(cnt) : "memory")
#define MBAR_ARRIVE_EXPECT(m, b) \
    asm volatile("mbarrier.arrive.expect_tx.shared.b64 _, [%0], %1;" :: "r"(m), "r"(b) : "memory")
#define MBARRIER_WAIT_PARITY(addr, par) do {                                           \
    uint32_t _m = (addr); uint32_t _p = (par); uint32_t _done;                         \
    asm volatile("{\n\t.reg .pred p;\n\t"                                              \
        "mbarrier.try_wait.parity.acquire.cta.shared::cta.b64 p, [%1], %2;\n\t"        \
        "selp.b32 %0, 1, 0, p;\n\t}" : "=r"(_done) : "r"(_m), "r"(_p) : "memory");     \
    if (!_done) {                                                                      \
        asm volatile("{\n\t.reg .pred P1;\n\tWL_%=:\n\t"                               \
            "mbarrier.try_wait.parity.acquire.cta.shared::cta.b64 P1, [%0], %1, 0x989680;\n\t" \
            "@P1 bra.uni WD_%=;\n\tbra.uni WL_%=;\n\tWD_%=:\n\t}"                      \
            :: "r"(_m), "r"(_p) : "memory");                                           \
    } } while (0)
#define FENCE_ASYNC() asm volatile("fence.proxy.async.shared::cta;" ::: "memory")

__device__ __forceinline__ void ldmx4(uint32_t* r, uint32_t addr) {
    asm volatile("ldmatrix.sync.aligned.m8n8.x4.shared.b16 {%0,%1,%2,%3}, [%4];"
                 : "=r"(r[0]), "=r"(r[1]), "=r"(r[2]), "=r"(r[3]) : "r"(addr));
}
__device__ __forceinline__ void mma16816(float* d, const uint32_t* a, const uint32_t* b) {
    asm volatile(
        "mma.sync.aligned.m16n8k16.row.col.f32.f16.f16.f32 "
        "{%0,%1,%2,%3}, {%4,%5,%6,%7}, {%8,%9}, {%0,%1,%2,%3};"
        : "+f"(d[0]), "+f"(d[1]), "+f"(d[2]), "+f"(d[3])
        : "r"(a[0]), "r"(a[1]), "r"(a[2]), "r"(a[3]), "r"(b[0]), "r"(b[1]));
}

// ---------------- small kernels ----------------
__global__ void zero_kernel(float* p, size_t n) {
    size_t i = (size_t)blockIdx.x * blockDim.x + threadIdx.x;
    size_t s = (size_t)gridDim.x * blockDim.x;
    for (; i < n; i += s) p[i] = 0.f;
}

template <int C>
__global__ void gn_stats(const float* __restrict__ x, int n, float* __restrict__ part) {
    const int CG = C / 4;
    const int RPB = 256 / CG;
    int tid = threadIdx.x;
    int cg = tid % CG;
    int rsub = tid / CG;
    float4 s = {0, 0, 0, 0}, q = {0, 0, 0, 0};
    for (long r = (long)blockIdx.x * RPB + rsub; r < n; r += (long)gridDim.x * RPB) {
        float4 v = *(const float4*)(x + r * C + cg * 4);
        s.x += v.x; s.y += v.y; s.z += v.z; s.w += v.w;
        q.x += v.x * v.x; q.y += v.y * v.y; q.z += v.z * v.z; q.w += v.w * v.w;
    }
    __shared__ float4 sh[256], sq[256];
    sh[tid] = s; sq[tid] = q;
    __syncthreads();
    if (rsub == 0) {
        for (int j = 1; j < RPB; j++) {
            float4 t = sh[j * CG + cg];
            s.x += t.x; s.y += t.y; s.z += t.z; s.w += t.w;
            t = sq[j * CG + cg];
            q.x += t.x; q.y += t.y; q.z += t.z; q.w += t.w;
        }
        *(float4*)&part[blockIdx.x * C + cg * 4] = s;
        *(float4*)&part[NB * C + blockIdx.x * C + cg * 4] = q;
    }
}

template <int C, int CPG>
__global__ void gn_finalize(const float* __restrict__ part, const float* __restrict__ w,
                            const float* __restrict__ b, float rcount) {
    int c = threadIdx.x;
    float s = 0.f, q = 0.f;
    for (int blk = 0; blk < NB; blk++) {
        s += part[blk * C + c];
        q += part[NB * C + blk * C + c];
    }
    __shared__ float cs[256], cq[256];
    cs[c] = s; cq[c] = q;
    __syncthreads();
    __shared__ float mu[32], rs[32];
    if (c < C / CPG) {
        float S = 0.f, Q = 0.f;
        for (int j = 0; j < CPG; j++) { S += cs[c * CPG + j]; Q += cq[c * CPG + j]; }
        float m = S * rcount;
        float v = Q * rcount - m * m;
        mu[c] = m;
        rs[c] = rsqrtf(v + 1e-5f);
    }
    __syncthreads();
    int g = c / CPG;
    float sc = w[c] * rs[g];
    g_scale[c] = sc;
    g_shift[c] = b[c] - mu[g] * sc;
}

__global__ void downsample_kernel(const float* __restrict__ feats,
                                  const int* __restrict__ seg, int n) {
    long t = (long)blockIdx.x * blockDim.x + threadIdx.x;
    if (t >= (long)n * 32) return;
    int row = (int)(t >> 5);
    int q = (int)(t & 31);
    int c = q * 4;
    int s = seg[row];
    float4 f = *(const float4*)(feats + (long)row * 128 + c);
    float4 sc = *(const float4*)(g_scale + c);
    float4 sh = *(const float4*)(g_shift + c);
    float h0 = silu_f(f.x * sc.x + sh.x);
    float h1 = silu_f(f.y * sc.y + sh.y);
    float h2 = silu_f(f.z * sc.z + sh.z);
    float h3 = silu_f(f.w * sc.w + sh.w);
    float* hp = g_A + (long)s * 128 + c;
    float* xp = g_B + (long)s * 128 + c;
    atomicAdd(hp + 0, h0); atomicAdd(hp + 1, h1);
    atomicAdd(hp + 2, h2); atomicAdd(hp + 3, h3);
    atomicAdd(xp + 0, f.x); atomicAdd(xp + 1, f.y);
    atomicAdd(xp + 2, f.z); atomicAdd(xp + 3, f.w);
    if (q == 0) atomicAdd(g_cnt + s, 1.f);
}

__global__ void finalize_down(int M) {
    long t = (long)blockIdx.x * blockDim.x + threadIdx.x;
    if (t >= (long)M * 32) return;
    int row = (int)(t >> 5);
    int c = (int)(t & 31) * 4;
    float ic = 1.f / fmaxf(g_cnt[row], 1.f);
    size_t base = (size_t)row * 128 + c;
    float4 va = *(const float4*)(g_A + base);
    float4 vb = *(const float4*)(g_B + base);
    g_hd[base + 0] = __float2half(va.x * ic);
    g_hd[base + 1] = __float2half(va.y * ic);
    g_hd[base + 2] = __float2half(va.z * ic);
    g_hd[base + 3] = __float2half(va.w * ic);
    g_xd[base + 0] = __float2half(vb.x * ic);
    g_xd[base + 1] = __float2half(vb.y * ic);
    g_xd[base + 2] = __float2half(vb.z * ic);
    g_xd[base + 3] = __float2half(vb.w * ic);
}

__global__ void apply_gn2(int M) {
    long t = (long)blockIdx.x * blockDim.x + threadIdx.x;
    if (t >= (long)M * 64) return;
    int row = (int)(t >> 6);
    int c = (int)(t & 63) * 4;
    size_t base = (size_t)row * 256 + c;
    float4 v = *(const float4*)(g_C + base);
    float4 sc = *(const float4*)(g_scale + c);
    float4 sh = *(const float4*)(g_shift + c);
    g_h2[base + 0] = __float2half(silu_f(v.x * sc.x + sh.x));
    g_h2[base + 1] = __float2half(silu_f(v.y * sc.y + sh.y));
    g_h2[base + 2] = __float2half(silu_f(v.z * sc.z + sh.z));
    g_h2[base + 3] = __float2half(silu_f(v.w * sc.w + sh.w));
}

// transpose + fp16 + CHUNK/SWIZZLE: out elt = [(k*NCH+ch)*256 + n]*32 + (q^((n>>1)&3))*8 + o
template <int CIN>
__global__ void prep_w(const float* __restrict__ W, fh* __restrict__ wo, int total) {
    int idx = blockIdx.x * blockDim.x + threadIdx.x;
    int stride = gridDim.x * blockDim.x;
    const int NCH = CIN / 32;
    for (; idx < total; idx += stride) {
        int c = idx % CIN;
        int n = (idx / CIN) % 256;
        int k = idx / (CIN * 256);
        float v = W[((size_t)k * CIN + c) * 256 + n];
        int ch = c >> 5, q = (c >> 3) & 3, o = c & 7;
        size_t dst = ((size_t)(k * NCH + ch) * 256 + n) * 32 + ((q ^ ((n >> 1) & 3)) << 3) + o;
        wo[dst] = __float2half(v);
    }
}

// ---------------- HMMA gather-conv: fp16, tile 128x256, 512 thr, occ 1 ----------
// CTA 512 thr / 16 warps; warp grid 4x4 -> warp tile 32(M)x64(N) (64 accums,
// ~95 live regs, fits the 128-reg cap at 512 threads -> no spill [vs R4's 170]).
// Chunks (tap, k0=32): A 128x32 fp16 cp.async (1 piece/thread, zero-fill);
// B 256x32 fp16 via 1 bulk copy of the whole pre-swizzled 16KB block.
// Halves BOTH B traffic (128-row tiles) and A traffic (no N-split) vs R9.
// SMEM: A 4x8KB @0, B 4x16KB @32768, mbars @98304, nid @98336 (28*128 ints).
static constexpr int CONV_SMEM = 98336 + 28 * 128 * 4;

template <int CIN, bool FUSE_SKIP>
__global__ __launch_bounds__(512, 1) void conv_hmma(
    const fh* __restrict__ x, const fh* __restrict__ w,
    const fh* __restrict__ sx, const fh* __restrict__ sw,
    const float* __restrict__ bias, const float* __restrict__ bias2,
    const int* __restrict__ nbr, float* __restrict__ out, int M) {
    extern __shared__ char smem[];
    constexpr int NCH = CIN / 32;
    constexpr int NREG = 27 * NCH;
    constexpr int TC = NREG + (FUSE_SKIP ? 4 : 0);
    constexpr int NT = FUSE_SKIP ? 28 : 27;
    const uint32_t sbase = smem_u32(smem);
    const uint32_t mbars = sbase + 98304;
    int* nid = (int*)(smem + 98336);
    const int tid = threadIdx.x;
    const int mbase = blockIdx.x * 128;
    const int lane = tid & 31;
    const int wm = (tid >> 5) >> 2;   // 0..3
    const int wn = (tid >> 5) & 3;    // 0..3

    if (tid == 0) {
        MBARRIER_INIT(mbars + 0, 1);
        MBARRIER_INIT(mbars + 8, 1);
        MBARRIER_INIT(mbars + 16, 1);
        MBARRIER_INIT(mbars + 24, 1);
    }
    for (int u = tid; u < NT * 128; u += 512) {
        int tap = u >> 7;
        int r = mbase + (u & 127);
        nid[u] = (tap == 27) ? ((r < M) ? r : -1)
                             : ((r < M) ? nbr[(size_t)r * 27 + tap] : -1);
    }
    __syncthreads();

    float d[2][8][4];
#pragma unroll
    for (int a = 0; a < 2; a++)
#pragma unroll
        for (int b = 0; b < 8; b++)
#pragma unroll
            for (int c = 0; c < 4; c++) d[a][b][c] = 0.f;

    // issue chunk i: A via cp.async (512 pieces, 1/thread); B via 1 bulk copy
    auto issueC = [&](int i) {
        int tap, c0, cin, ch;
        const fh *ax, *bw;
        if (i < NREG) {
            tap = i / NCH; ch = i % NCH; c0 = ch * 32; cin = CIN;
            ax = x;
            bw = w + (size_t)(tap * NCH + ch) * 8192;
        } else {
            tap = 27; ch = i - NREG; c0 = ch * 32; cin = 128;
            ax = sx;
            bw = sw + (size_t)ch * 8192;
        }
        const int* nt = nid + tap * 128;
        const uint32_t ab = sbase + (i & 3) * 8192;
        const uint32_t bb = sbase + 32768 + (i & 3) * 16384;
        if (tid == 0) {
            FENCE_ASYNC();
            MBAR_ARRIVE_EXPECT(mbars + (i & 3) * 8, 16384u);
            cp_bulk_g2s(bb, bw, 16384u, mbars + (i & 3) * 8);
        }
        {
            int r = tid >> 2, q = tid & 3;
            int src = nt[r];
            const fh* sp = (src >= 0) ? (ax + (size_t)src * cin + c0 + q * 8)
                                      : (const fh*)g_zrow;
            cp_async16z(ab + r * 64 + ((q ^ ((r >> 1) & 3)) << 4),
                        sp, (src >= 0) ? 16u : 0u);
        }
        cp_commit();
    };

    issueC(0);
    if (TC > 1) issueC(1);
    if (TC > 2) issueC(2);

    for (int i = 0; i < TC; i++) {
        int newest = (TC - 1 < i + 2) ? (TC - 1) : (i + 2);
        int ahead = newest - i;
        if (ahead >= 2) cp_wait2();
        else if (ahead == 1) cp_wait1();
        else cp_wait0();
        MBARRIER_WAIT_PARITY(mbars + (i & 3) * 8, (i >> 2) & 1);
        __syncthreads();
        if (i + 3 < TC) issueC(i + 3);   // writes buf (i-1)&3: drained by sync

        const uint32_t ab = sbase + (i & 3) * 8192;
        const uint32_t bb = sbase + 32768 + (i & 3) * 16384;
#pragma unroll
        for (int ks = 0; ks < 2; ks++) {
            uint32_t ah[2][4];
            const int u = ks * 2 + ((lane >> 4) & 1);
#pragma unroll
            for (int mt = 0; mt < 2; mt++) {
                int row = wm * 32 + mt * 16 + (lane & 15);
                ldmx4(ah[mt], ab + row * 64 + ((u ^ ((row >> 1) & 3)) << 4));
            }
            const int brow = (lane & 7) + ((lane & 16) ? 8 : 0);
            const int bu = ks * 2 + ((lane >> 3) & 1);
#pragma unroll
            for (int p = 0; p < 4; p++) {
                int nl = wn * 64 + p * 16 + brow;
                uint32_t bh[4];
                ldmx4(bh, bb + nl * 64 + ((bu ^ ((nl >> 1) & 3)) << 4));
#pragma unroll
                for (int mt = 0; mt < 2; mt++) {
                    mma16816(d[mt][2 * p + 0], ah[mt], &bh[0]);
                    mma16816(d[mt][2 * p + 1], ah[mt], &bh[2]);
                }
            }
        }
    }

    // epilogue: direct global stores
#pragma unroll
    for (int mt = 0; mt < 2; mt++) {
        int r0 = mbase + wm * 32 + mt * 16 + lane / 4;
#pragma unroll
        for (int t = 0; t < 8; t++) {
            int gc = wn * 64 + t * 8 + (lane % 4) * 2;
            float bx = bias[gc], by = bias[gc + 1];
            if (FUSE_SKIP) { bx += bias2[gc]; by += bias2[gc + 1]; }
            if (r0 < M) {
                float2 v = {d[mt][t][0] + bx, d[mt][t][1] + by};
                *(float2*)(out + (size_t)r0 * 256 + gc) = v;
            }
            if (r0 + 8 < M) {
                float2 v = {d[mt][t][2] + bx, d[mt][t][3] + by};
                *(float2*)(out + (size_t)(r0 + 8) * 256 + gc) = v;
            }
        }
    }
}

// ---------------- launch ----------------
extern "C" void kernel_launch(void* const* d_in, const int* in_sizes, int n_in,
                              void* d_out, int out_size) {
    const float* feats = (const float*)d_in[0];
    const float* gn1_w = (const float*)d_in[1];
    const float* gn1_b = (const float*)d_in[2];
    const float* W1    = (const float*)d_in[3];
    const float* b1    = (const float*)d_in[4];
    const float* gn2_w = (const float*)d_in[5];
    const float* gn2_b = (const float*)d_in[6];
    const float* W2    = (const float*)d_in[7];
    const float* b2    = (const float*)d_in[8];
    const float* Wskip = (const float*)d_in[9];
    const float* bskip = (const float*)d_in[10];
    const int* pool_seg = (const int*)d_in[11];
    const int* nbr_idx  = (const int*)d_in[12];
    float* out = (float*)d_out;

    int N = in_sizes[0] / 128;
    int M = in_sizes[12] / 27;

    float *A, *B, *C, *cnt, *part;
    cudaGetSymbolAddress((void**)&A, g_A);
    cudaGetSymbolAddress((void**)&B, g_B);
    cudaGetSymbolAddress((void**)&C, g_C);
    cudaGetSymbolAddress((void**)&cnt, g_cnt);
    cudaGetSymbolAddress((void**)&part, g_part);
    fh *hd, *xd, *h2, *W1p, *W2p, *WSp;
    cudaGetSymbolAddress((void**)&hd, g_hd);
    cudaGetSymbolAddress((void**)&xd, g_xd);
    cudaGetSymbolAddress((void**)&h2, g_h2);
    cudaGetSymbolAddress((void**)&W1p, g_W1);
    cudaGetSymbolAddress((void**)&W2p, g_W2);
    cudaGetSymbolAddress((void**)&WSp, g_WS);

    cudaFuncSetAttribute(conv_hmma<128, false>,
                         cudaFuncAttributeMaxDynamicSharedMemorySize, CONV_SMEM);
    cudaFuncSetAttribute(conv_hmma<256, true>,
                         cudaFuncAttributeMaxDynamicSharedMemorySize, CONV_SMEM);

    // zero atomic accumulators (graph replays -> re-zero every launch)
    zero_kernel<<<4096, 256>>>(A, (size_t)M * 128);
    zero_kernel<<<4096, 256>>>(B, (size_t)M * 128);
    zero_kernel<<<256, 256>>>(cnt, (size_t)M);

    // weight transpose + fp16 + chunked/pre-swizzled layout
    prep_w<128><<<1024, 256>>>(W1, W1p, 27 * 256 * 128);
    prep_w<256><<<2048, 256>>>(W2, W2p, 27 * 256 * 256);
    prep_w<128><<<128, 256>>>(Wskip, WSp, 256 * 128);

    // GN1 stats + finalize
    gn_stats<128><<<NB, 256>>>(feats, N, part);
    gn_finalize<128, 4><<<1, 128>>>(part, gn1_w, gn1_b, 1.f / ((float)N * 4.f));

    // GN1 apply + SiLU + segment sums; then means -> fp16 planes
    long dthreads = (long)N * 32;
    downsample_kernel<<<(int)((dthreads + 255) / 256), 256>>>(feats, pool_seg, N);
    long fthreads = (long)M * 32;
    finalize_down<<<(int)((fthreads + 255) / 256), 256>>>(M);

    int nconv = (M + 127) / 128;

    // conv1: h1 = conv(h_d, W1) + b1
    conv_hmma<128, false><<<nconv, 512, CONV_SMEM>>>(
        hd, W1p, nullptr, nullptr, b1, nullptr, nbr_idx, C, M);

    // GN2 stats + finalize + apply (emits h2 fp16 plane)
    gn_stats<256><<<NB, 256>>>(C, M, part);
    gn_finalize<256, 8><<<1, 256>>>(part, gn2_w, gn2_b, 1.f / ((float)M * 8.f));
    long athreads = (long)M * 64;
    apply_gn2<<<(int)((athreads + 255) / 256), 256>>>(M);

    // conv2 + fused skip: out = conv(h2, W2) + b2 + x_d @ Wskip + bskip
    conv_hmma<256, true><<<nconv, 512, CONV_SMEM>>>(
        h2, W2p, xd, WSp, b2, bskip, nbr_idx, out, M);
}

// round 11
// speedup vs baseline: 1.2608x; 1.2608x over previous
#include <cuda_runtime.h>
#include <cuda_bf16.h>
#include <cuda_fp16.h>
#include <cstdint>

#define MMAX 200704
#define NB 256

typedef __half fh;

// ---------------- scratch (device globals; no allocation allowed) ----------------
__device__ float g_A[(size_t)MMAX * 128];   // h segment-sum accumulator
__device__ float g_B[(size_t)MMAX * 128];   // x segment-sum accumulator
__device__ float g_C[(size_t)MMAX * 256];   // h1 (conv1 out, fp32 for GN2 stats)
__device__ float g_cnt[MMAX];
__device__ float g_part[2 * NB * 256];
__device__ float g_scale[256];
__device__ float g_shift[256];
__device__ __align__(16) fh g_zrow[64];     // safe src for zero-fill cp.async
// fp16 operand planes (single plane each)
__device__ fh g_hd[(size_t)MMAX * 128];
__device__ fh g_xd[(size_t)MMAX * 128];
__device__ fh g_h2[(size_t)MMAX * 256];
// weights: chunked+pre-swizzled layout [tap*NCH+ch][n=256][32] (fp16, 16KB blocks)
__device__ __align__(16) fh g_W1[27 * 256 * 128];
__device__ __align__(16) fh g_W2[27 * 256 * 256];
__device__ __align__(16) fh g_WS[256 * 128];

__device__ __forceinline__ float silu_f(float x) { return x / (1.f + __expf(-x)); }

__device__ __forceinline__ uint32_t smem_u32(const void* p) {
    uint32_t a;
    asm("{ .reg .u64 t; cvta.to.shared.u64 t, %1; cvt.u32.u64 %0, t; }" : "=r"(a) : "l"(p));
    return a;
}
// zero-fill form: src-size=0 -> writes 16 zero bytes, NO global read issued
__device__ __forceinline__ void cp_async16z(uint32_t dst, const void* src, uint32_t srcsz) {
    asm volatile("cp.async.cg.shared.global [%0], [%1], 16, %2;"
                 :: "r"(dst), "l"(src), "r"(srcsz));
}
__device__ __forceinline__ void cp_commit() {
    asm volatile("cp.async.commit_group;" ::: "memory");
}
__device__ __forceinline__ void cp_wait0() { asm volatile("cp.async.wait_group 0;" ::: "memory"); }
__device__ __forceinline__ void cp_wait1() { asm volatile("cp.async.wait_group 1;" ::: "memory"); }
__device__ __forceinline__ void cp_wait2() { asm volatile("cp.async.wait_group 2;" ::: "memory"); }
// bulk g2s copy completing on an mbarrier (sm_90 base feature)
__device__ __forceinline__ void cp_bulk_g2s(uint32_t dst, const void* src, uint32_t bytes,
                                            uint32_t mbar) {
    asm volatile(
        "cp.async.bulk.shared::cta.global.mbarrier::complete_tx::bytes [%0], [%1], %2, [%3];"
        :: "r"(dst), "l"(src), "r"(bytes), "r"(mbar) : "memory");
}
#define MBARRIER_INIT(addr, cnt) \
    asm volatile("mbarrier.init.shared.b64 [%0], %1;" :: "r"(addr), "r"(cnt) : "memory")
#define MBAR_ARRIVE_EXPECT(m, b) \
    asm volatile("mbarrier.arrive.expect_tx.shared.b64 _, [%0], %1;" :: "r"(m), "r"(b) : "memory")
#define MBARRIER_WAIT_PARITY(addr, par) do {                                           \
    uint32_t _m = (addr); uint32_t _p = (par); uint32_t _done;                         \
    asm volatile("{\n\t.reg .pred p;\n\t"                                              \
        "mbarrier.try_wait.parity.acquire.cta.shared::cta.b64 p, [%1], %2;\n\t"        \
        "selp.b32 %0, 1, 0, p;\n\t}" : "=r"(_done) : "r"(_m), "r"(_p) : "memory");     \
    if (!_done) {                                                                      \
        asm volatile("{\n\t.reg .pred P1;\n\tWL_%=:\n\t"                               \
            "mbarrier.try_wait.parity.acquire.cta.shared::cta.b64 P1, [%0], %1, 0x989680;\n\t" \
            "@P1 bra.uni WD_%=;\n\tbra.uni WL_%=;\n\tWD_%=:\n\t}"                      \
            :: "r"(_m), "r"(_p) : "memory");                                           \
    } } while (0)
#define FENCE_ASYNC() asm volatile("fence.proxy.async.shared::cta;" ::: "memory")

__device__ __forceinline__ void ldmx4(uint32_t* r, uint32_t addr) {
    asm volatile("ldmatrix.sync.aligned.m8n8.x4.shared.b16 {%0,%1,%2,%3}, [%4];"
                 : "=r"(r[0]), "=r"(r[1]), "=r"(r[2]), "=r"(r[3]) : "r"(addr));
}
__device__ __forceinline__ void mma16816(float* d, const uint32_t* a, const uint32_t* b) {
    asm volatile(
        "mma.sync.aligned.m16n8k16.row.col.f32.f16.f16.f32 "
        "{%0,%1,%2,%3}, {%4,%5,%6,%7}, {%8,%9}, {%0,%1,%2,%3};"
        : "+f"(d[0]), "+f"(d[1]), "+f"(d[2]), "+f"(d[3])
        : "r"(a[0]), "r"(a[1]), "r"(a[2]), "r"(a[3]), "r"(b[0]), "r"(b[1]));
}

// ---------------- small kernels ----------------
__global__ void zero_kernel(float* p, size_t n) {
    size_t i = (size_t)blockIdx.x * blockDim.x + threadIdx.x;
    size_t s = (size_t)gridDim.x * blockDim.x;
    for (; i < n; i += s) p[i] = 0.f;
}

template <int C>
__global__ void gn_stats(const float* __restrict__ x, int n, float* __restrict__ part) {
    const int CG = C / 4;
    const int RPB = 256 / CG;
    int tid = threadIdx.x;
    int cg = tid % CG;
    int rsub = tid / CG;
    float4 s = {0, 0, 0, 0}, q = {0, 0, 0, 0};
    for (long r = (long)blockIdx.x * RPB + rsub; r < n; r += (long)gridDim.x * RPB) {
        float4 v = *(const float4*)(x + r * C + cg * 4);
        s.x += v.x; s.y += v.y; s.z += v.z; s.w += v.w;
        q.x += v.x * v.x; q.y += v.y * v.y; q.z += v.z * v.z; q.w += v.w * v.w;
    }
    __shared__ float4 sh[256], sq[256];
    sh[tid] = s; sq[tid] = q;
    __syncthreads();
    if (rsub == 0) {
        for (int j = 1; j < RPB; j++) {
            float4 t = sh[j * CG + cg];
            s.x += t.x; s.y += t.y; s.z += t.z; s.w += t.w;
            t = sq[j * CG + cg];
            q.x += t.x; q.y += t.y; q.z += t.z; q.w += t.w;
        }
        *(float4*)&part[blockIdx.x * C + cg * 4] = s;
        *(float4*)&part[NB * C + blockIdx.x * C + cg * 4] = q;
    }
}

template <int C, int CPG>
__global__ void gn_finalize(const float* __restrict__ part, const float* __restrict__ w,
                            const float* __restrict__ b, float rcount) {
    int c = threadIdx.x;
    float s = 0.f, q = 0.f;
    for (int blk = 0; blk < NB; blk++) {
        s += part[blk * C + c];
        q += part[NB * C + blk * C + c];
    }
    __shared__ float cs[256], cq[256];
    cs[c] = s; cq[c] = q;
    __syncthreads();
    __shared__ float mu[32], rs[32];
    if (c < C / CPG) {
        float S = 0.f, Q = 0.f;
        for (int j = 0; j < CPG; j++) { S += cs[c * CPG + j]; Q += cq[c * CPG + j]; }
        float m = S * rcount;
        float v = Q * rcount - m * m;
        mu[c] = m;
        rs[c] = rsqrtf(v + 1e-5f);
    }
    __syncthreads();
    int g = c / CPG;
    float sc = w[c] * rs[g];
    g_scale[c] = sc;
    g_shift[c] = b[c] - mu[g] * sc;
}

__global__ void downsample_kernel(const float* __restrict__ feats,
                                  const int* __restrict__ seg, int n) {
    long t = (long)blockIdx.x * blockDim.x + threadIdx.x;
    if (t >= (long)n * 32) return;
    int row = (int)(t >> 5);
    int q = (int)(t & 31);
    int c = q * 4;
    int s = seg[row];
    float4 f = *(const float4*)(feats + (long)row * 128 + c);
    float4 sc = *(const float4*)(g_scale + c);
    float4 sh = *(const float4*)(g_shift + c);
    float h0 = silu_f(f.x * sc.x + sh.x);
    float h1 = silu_f(f.y * sc.y + sh.y);
    float h2 = silu_f(f.z * sc.z + sh.z);
    float h3 = silu_f(f.w * sc.w + sh.w);
    float* hp = g_A + (long)s * 128 + c;
    float* xp = g_B + (long)s * 128 + c;
    atomicAdd(hp + 0, h0); atomicAdd(hp + 1, h1);
    atomicAdd(hp + 2, h2); atomicAdd(hp + 3, h3);
    atomicAdd(xp + 0, f.x); atomicAdd(xp + 1, f.y);
    atomicAdd(xp + 2, f.z); atomicAdd(xp + 3, f.w);
    if (q == 0) atomicAdd(g_cnt + s, 1.f);
}

__global__ void finalize_down(int M) {
    long t = (long)blockIdx.x * blockDim.x + threadIdx.x;
    if (t >= (long)M * 32) return;
    int row = (int)(t >> 5);
    int c = (int)(t & 31) * 4;
    float ic = 1.f / fmaxf(g_cnt[row], 1.f);
    size_t base = (size_t)row * 128 + c;
    float4 va = *(const float4*)(g_A + base);
    float4 vb = *(const float4*)(g_B + base);
    g_hd[base + 0] = __float2half(va.x * ic);
    g_hd[base + 1] = __float2half(va.y * ic);
    g_hd[base + 2] = __float2half(va.z * ic);
    g_hd[base + 3] = __float2half(va.w * ic);
    g_xd[base + 0] = __float2half(vb.x * ic);
    g_xd[base + 1] = __float2half(vb.y * ic);
    g_xd[base + 2] = __float2half(vb.z * ic);
    g_xd[base + 3] = __float2half(vb.w * ic);
}

__global__ void apply_gn2(int M) {
    long t = (long)blockIdx.x * blockDim.x + threadIdx.x;
    if (t >= (long)M * 64) return;
    int row = (int)(t >> 6);
    int c = (int)(t & 63) * 4;
    size_t base = (size_t)row * 256 + c;
    float4 v = *(const float4*)(g_C + base);
    float4 sc = *(const float4*)(g_scale + c);
    float4 sh = *(const float4*)(g_shift + c);
    g_h2[base + 0] = __float2half(silu_f(v.x * sc.x + sh.x));
    g_h2[base + 1] = __float2half(silu_f(v.y * sc.y + sh.y));
    g_h2[base + 2] = __float2half(silu_f(v.z * sc.z + sh.z));
    g_h2[base + 3] = __float2half(silu_f(v.w * sc.w + sh.w));
}

// transpose + fp16 + CHUNK/SWIZZLE: out elt = [(k*NCH+ch)*256 + n]*32 + (q^((n>>1)&3))*8 + o
template <int CIN>
__global__ void prep_w(const float* __restrict__ W, fh* __restrict__ wo, int total) {
    int idx = blockIdx.x * blockDim.x + threadIdx.x;
    int stride = gridDim.x * blockDim.x;
    const int NCH = CIN / 32;
    for (; idx < total; idx += stride) {
        int c = idx % CIN;
        int n = (idx / CIN) % 256;
        int k = idx / (CIN * 256);
        float v = W[((size_t)k * CIN + c) * 256 + n];
        int ch = c >> 5, q = (c >> 3) & 3, o = c & 7;
        size_t dst = ((size_t)(k * NCH + ch) * 256 + n) * 32 + ((q ^ ((n >> 1) & 3)) << 3) + o;
        wo[dst] = __float2half(v);
    }
}

// ---------------- HMMA gather-conv: fp16, tile 128(M)x128(N), 256 thr, occ 2 ----
// Grid = (M/128 tiles) x 2 N-halves. CTA 256 thr / 8 warps; warp grid 4(M)x2(N);
// warp tile 32x64 (64 accums; ~100 live regs < 128-reg cap at occ 2).
// Halves B traffic vs R9 (128-row tiles) while KEEPING occupancy 2 (the R10
// lesson: occ-2 latency hiding dominates raw traffic reduction).
// Chunks (tap, k0=32): A 128x32 fp16 cp.async (2 pieces/thread, zero-fill);
// B 128x32 fp16 via 1 bulk copy of the contiguous pre-swizzled half-block.
// SMEM: A 4x8KB @0, B 4x8KB @32768, mbars @65536, nid @65568 (28*128 ints).
static constexpr int CONV_SMEM = 65568 + 28 * 128 * 4;

template <int CIN, bool FUSE_SKIP>
__global__ __launch_bounds__(256, 2) void conv_hmma(
    const fh* __restrict__ x, const fh* __restrict__ w,
    const fh* __restrict__ sx, const fh* __restrict__ sw,
    const float* __restrict__ bias, const float* __restrict__ bias2,
    const int* __restrict__ nbr, float* __restrict__ out, int M) {
    extern __shared__ char smem[];
    constexpr int NCH = CIN / 32;
    constexpr int NREG = 27 * NCH;
    constexpr int TC = NREG + (FUSE_SKIP ? 4 : 0);
    constexpr int NT = FUSE_SKIP ? 28 : 27;
    const uint32_t sbase = smem_u32(smem);
    const uint32_t mbars = sbase + 65536;
    int* nid = (int*)(smem + 65568);
    const int tid = threadIdx.x;
    const int mbase = (blockIdx.x >> 1) * 128;
    const int n0 = (blockIdx.x & 1) * 128;
    const int lane = tid & 31;
    const int wm = (tid >> 5) >> 1;   // 0..3
    const int wn = (tid >> 5) & 1;    // 0..1

    if (tid == 0) {
        MBARRIER_INIT(mbars + 0, 1);
        MBARRIER_INIT(mbars + 8, 1);
        MBARRIER_INIT(mbars + 16, 1);
        MBARRIER_INIT(mbars + 24, 1);
    }
    for (int u = tid; u < NT * 128; u += 256) {
        int tap = u >> 7;
        int r = mbase + (u & 127);
        nid[u] = (tap == 27) ? ((r < M) ? r : -1)
                             : ((r < M) ? nbr[(size_t)r * 27 + tap] : -1);
    }
    __syncthreads();

    float d[2][8][4];
#pragma unroll
    for (int a = 0; a < 2; a++)
#pragma unroll
        for (int b = 0; b < 8; b++)
#pragma unroll
            for (int c = 0; c < 4; c++) d[a][b][c] = 0.f;

    // issue chunk i: A via cp.async (512 pieces, 2/thread); B via 1 bulk copy
    auto issueC = [&](int i) {
        int tap, c0, cin, ch;
        const fh *ax, *bw;
        if (i < NREG) {
            tap = i / NCH; ch = i % NCH; c0 = ch * 32; cin = CIN;
            ax = x;
            bw = w + (size_t)(tap * NCH + ch) * 8192 + n0 * 32;
        } else {
            tap = 27; ch = i - NREG; c0 = ch * 32; cin = 128;
            ax = sx;
            bw = sw + (size_t)ch * 8192 + n0 * 32;
        }
        const int* nt = nid + tap * 128;
        const uint32_t ab = sbase + (i & 3) * 8192;
        const uint32_t bb = sbase + 32768 + (i & 3) * 8192;
        if (tid == 0) {
            FENCE_ASYNC();
            MBAR_ARRIVE_EXPECT(mbars + (i & 3) * 8, 8192u);
            cp_bulk_g2s(bb, bw, 8192u, mbars + (i & 3) * 8);
        }
#pragma unroll
        for (int wv = 0; wv < 2; wv++) {
            int u = tid + wv * 256;
            int r = u >> 2, q = u & 3;
            int src = nt[r];
            const fh* sp = (src >= 0) ? (ax + (size_t)src * cin + c0 + q * 8)
                                      : (const fh*)g_zrow;
            cp_async16z(ab + r * 64 + ((q ^ ((r >> 1) & 3)) << 4),
                        sp, (src >= 0) ? 16u : 0u);
        }
        cp_commit();
    };

    issueC(0);
    if (TC > 1) issueC(1);
    if (TC > 2) issueC(2);

    for (int i = 0; i < TC; i++) {
        int newest = (TC - 1 < i + 2) ? (TC - 1) : (i + 2);
        int ahead = newest - i;
        if (ahead >= 2) cp_wait2();
        else if (ahead == 1) cp_wait1();
        else cp_wait0();
        MBARRIER_WAIT_PARITY(mbars + (i & 3) * 8, (i >> 2) & 1);
        __syncthreads();
        if (i + 3 < TC) issueC(i + 3);   // writes buf (i-1)&3: drained by sync

        const uint32_t ab = sbase + (i & 3) * 8192;
        const uint32_t bb = sbase + 32768 + (i & 3) * 8192;
#pragma unroll
        for (int ks = 0; ks < 2; ks++) {
            uint32_t ah[2][4];
            const int u = ks * 2 + ((lane >> 4) & 1);
#pragma unroll
            for (int mt = 0; mt < 2; mt++) {
                int row = wm * 32 + mt * 16 + (lane & 15);
                ldmx4(ah[mt], ab + row * 64 + ((u ^ ((row >> 1) & 3)) << 4));
            }
            const int brow = (lane & 7) + ((lane & 16) ? 8 : 0);
            const int bu = ks * 2 + ((lane >> 3) & 1);
#pragma unroll
            for (int p = 0; p < 4; p++) {
                int nl = wn * 64 + p * 16 + brow;   // local col in [0,128)
                uint32_t bh[4];
                ldmx4(bh, bb + nl * 64 + ((bu ^ ((nl >> 1) & 3)) << 4));
#pragma unroll
                for (int mt = 0; mt < 2; mt++) {
                    mma16816(d[mt][2 * p + 0], ah[mt], &bh[0]);
                    mma16816(d[mt][2 * p + 1], ah[mt], &bh[2]);
                }
            }
        }
    }

    // epilogue: direct global stores
#pragma unroll
    for (int mt = 0; mt < 2; mt++) {
        int r0 = mbase + wm * 32 + mt * 16 + lane / 4;
#pragma unroll
        for (int t = 0; t < 8; t++) {
            int gc = n0 + wn * 64 + t * 8 + (lane % 4) * 2;
            float bx = bias[gc], by = bias[gc + 1];
            if (FUSE_SKIP) { bx += bias2[gc]; by += bias2[gc + 1]; }
            if (r0 < M) {
                float2 v = {d[mt][t][0] + bx, d[mt][t][1] + by};
                *(float2*)(out + (size_t)r0 * 256 + gc) = v;
            }
            if (r0 + 8 < M) {
                float2 v = {d[mt][t][2] + bx, d[mt][t][3] + by};
                *(float2*)(out + (size_t)(r0 + 8) * 256 + gc) = v;
            }
        }
    }
}

// ---------------- launch ----------------
extern "C" void kernel_launch(void* const* d_in, const int* in_sizes, int n_in,
                              void* d_out, int out_size) {
    const float* feats = (const float*)d_in[0];
    const float* gn1_w = (const float*)d_in[1];
    const float* gn1_b = (const float*)d_in[2];
    const float* W1    = (const float*)d_in[3];
    const float* b1    = (const float*)d_in[4];
    const float* gn2_w = (const float*)d_in[5];
    const float* gn2_b = (const float*)d_in[6];
    const float* W2    = (const float*)d_in[7];
    const float* b2    = (const float*)d_in[8];
    const float* Wskip = (const float*)d_in[9];
    const float* bskip = (const float*)d_in[10];
    const int* pool_seg = (const int*)d_in[11];
    const int* nbr_idx  = (const int*)d_in[12];
    float* out = (float*)d_out;

    int N = in_sizes[0] / 128;
    int M = in_sizes[12] / 27;

    float *A, *B, *C, *cnt, *part;
    cudaGetSymbolAddress((void**)&A, g_A);
    cudaGetSymbolAddress((void**)&B, g_B);
    cudaGetSymbolAddress((void**)&C, g_C);
    cudaGetSymbolAddress((void**)&cnt, g_cnt);
    cudaGetSymbolAddress((void**)&part, g_part);
    fh *hd, *xd, *h2, *W1p, *W2p, *WSp;
    cudaGetSymbolAddress((void**)&hd, g_hd);
    cudaGetSymbolAddress((void**)&xd, g_xd);
    cudaGetSymbolAddress((void**)&h2, g_h2);
    cudaGetSymbolAddress((void**)&W1p, g_W1);
    cudaGetSymbolAddress((void**)&W2p, g_W2);
    cudaGetSymbolAddress((void**)&WSp, g_WS);

    cudaFuncSetAttribute(conv_hmma<128, false>,
                         cudaFuncAttributeMaxDynamicSharedMemorySize, CONV_SMEM);
    cudaFuncSetAttribute(conv_hmma<256, true>,
                         cudaFuncAttributeMaxDynamicSharedMemorySize, CONV_SMEM);

    // zero atomic accumulators (graph replays -> re-zero every launch)
    zero_kernel<<<4096, 256>>>(A, (size_t)M * 128);
    zero_kernel<<<4096, 256>>>(B, (size_t)M * 128);
    zero_kernel<<<256, 256>>>(cnt, (size_t)M);

    // weight transpose + fp16 + chunked/pre-swizzled layout
    prep_w<128><<<1024, 256>>>(W1, W1p, 27 * 256 * 128);
    prep_w<256><<<2048, 256>>>(W2, W2p, 27 * 256 * 256);
    prep_w<128><<<128, 256>>>(Wskip, WSp, 256 * 128);

    // GN1 stats + finalize
    gn_stats<128><<<NB, 256>>>(feats, N, part);
    gn_finalize<128, 4><<<1, 128>>>(part, gn1_w, gn1_b, 1.f / ((float)N * 4.f));

    // GN1 apply + SiLU + segment sums; then means -> fp16 planes
    long dthreads = (long)N * 32;
    downsample_kernel<<<(int)((dthreads + 255) / 256), 256>>>(feats, pool_seg, N);
    long fthreads = (long)M * 32;
    finalize_down<<<(int)((fthreads + 255) / 256), 256>>>(M);

    int nconv = ((M + 127) / 128) * 2;   // x2 N-halves

    // conv1: h1 = conv(h_d, W1) + b1
    conv_hmma<128, false><<<nconv, 256, CONV_SMEM>>>(
        hd, W1p, nullptr, nullptr, b1, nullptr, nbr_idx, C, M);

    // GN2 stats + finalize + apply (emits h2 fp16 plane)
    gn_stats<256><<<NB, 256>>>(C, M, part);
    gn_finalize<256, 8><<<1, 256>>>(part, gn2_w, gn2_b, 1.f / ((float)M * 8.f));
    long athreads = (long)M * 64;
    apply_gn2<<<(int)((athreads + 255) / 256), 256>>>(M);

    // conv2 + fused skip: out = conv(h2, W2) + b2 + x_d @ Wskip + bskip
    conv_hmma<256, true><<<nconv, 256, CONV_SMEM>>>(
        h2, W2p, xd, WSp, b2, bskip, nbr_idx, out, M);
}

// round 12
// speedup vs baseline: 1.3208x; 1.0476x over previous
#include <cuda_runtime.h>
#include <cuda_bf16.h>
#include <cuda_fp16.h>
#include <cstdint>

#define MMAX 200704
#define NB 256

typedef __half fh;

// ---------------- scratch (device globals; no allocation allowed) ----------------
__device__ float g_A[(size_t)MMAX * 128];   // h segment-sum accumulator
__device__ float g_B[(size_t)MMAX * 128];   // x segment-sum accumulator
__device__ fh    g_C[(size_t)MMAX * 256];   // h1 (conv1 out, fp16)
__device__ float g_cnt[MMAX];
__device__ float g_part[2 * NB * 256];
__device__ float g_scale[256];
__device__ float g_shift[256];
__device__ __align__(16) fh g_zrow[64];     // safe src for zero-fill cp.async
// fp16 operand planes (single plane each)
__device__ fh g_hd[(size_t)MMAX * 128];
__device__ fh g_xd[(size_t)MMAX * 128];
__device__ fh g_h2[(size_t)MMAX * 256];
// weights: chunked+pre-swizzled layout [tap*NCH2+ch][n=256][64] (fp16, 32KB blocks,
// 128B rows with slot swizzle q^(n&7))
__device__ __align__(16) fh g_W1[27 * 256 * 128];
__device__ __align__(16) fh g_W2[27 * 256 * 256];
__device__ __align__(16) fh g_WS[256 * 128];

__device__ __forceinline__ float silu_f(float x) { return x / (1.f + __expf(-x)); }

__device__ __forceinline__ uint32_t smem_u32(const void* p) {
    uint32_t a;
    asm("{ .reg .u64 t; cvta.to.shared.u64 t, %1; cvt.u32.u64 %0, t; }" : "=r"(a) : "l"(p));
    return a;
}
// zero-fill form: src-size=0 -> writes 16 zero bytes, NO global read issued
__device__ __forceinline__ void cp_async16z(uint32_t dst, const void* src, uint32_t srcsz) {
    asm volatile("cp.async.cg.shared.global [%0], [%1], 16, %2;"
                 :: "r"(dst), "l"(src), "r"(srcsz));
}
__device__ __forceinline__ void cp_commit() {
    asm volatile("cp.async.commit_group;" ::: "memory");
}
__device__ __forceinline__ void cp_wait0() { asm volatile("cp.async.wait_group 0;" ::: "memory"); }
__device__ __forceinline__ void cp_wait1() { asm volatile("cp.async.wait_group 1;" ::: "memory"); }
// bulk g2s copy completing on an mbarrier (sm_90 base feature)
__device__ __forceinline__ void cp_bulk_g2s(uint32_t dst, const void* src, uint32_t bytes,
                                            uint32_t mbar) {
    asm volatile(
        "cp.async.bulk.shared::cta.global.mbarrier::complete_tx::bytes [%0], [%1], %2, [%3];"
        :: "r"(dst), "l"(src), "r"(bytes), "r"(mbar) : "memory");
}
#define MBARRIER_INIT(addr, cnt) \
    asm volatile("mbarrier.init.shared.b64 [%0], %1;" :: "r"(addr), "r"(cnt) : "memory")
#define MBAR_ARRIVE_EXPECT(m, b) \
    asm volatile("mbarrier.arrive.expect_tx.shared.b64 _, [%0], %1;" :: "r"(m), "r"(b) : "memory")
#define MBARRIER_WAIT_PARITY(addr, par) do {                                           \
    uint32_t _m = (addr); uint32_t _p = (par); uint32_t _done;                         \
    asm volatile("{\n\t.reg .pred p;\n\t"                                              \
        "mbarrier.try_wait.parity.acquire.cta.shared::cta.b64 p, [%1], %2;\n\t"        \
        "selp.b32 %0, 1, 0, p;\n\t}" : "=r"(_done) : "r"(_m), "r"(_p) : "memory");     \
    if (!_done) {                                                                      \
        asm volatile("{\n\t.reg .pred P1;\n\tWL_%=:\n\t"                               \
            "mbarrier.try_wait.parity.acquire.cta.shared::cta.b64 P1, [%0], %1, 0x989680;\n\t" \
            "@P1 bra.uni WD_%=;\n\tbra.uni WL_%=;\n\tWD_%=:\n\t}"                      \
            :: "r"(_m), "r"(_p) : "memory");                                           \
    } } while (0)
#define FENCE_ASYNC() asm volatile("fence.proxy.async.shared::cta;" ::: "memory")

__device__ __forceinline__ void ldmx4(uint32_t* r, uint32_t addr) {
    asm volatile("ldmatrix.sync.aligned.m8n8.x4.shared.b16 {%0,%1,%2,%3}, [%4];"
                 : "=r"(r[0]), "=r"(r[1]), "=r"(r[2]), "=r"(r[3]) : "r"(addr));
}
__device__ __forceinline__ void mma16816(float* d, const uint32_t* a, const uint32_t* b) {
    asm volatile(
        "mma.sync.aligned.m16n8k16.row.col.f32.f16.f16.f32 "
        "{%0,%1,%2,%3}, {%4,%5,%6,%7}, {%8,%9}, {%0,%1,%2,%3};"
        : "+f"(d[0]), "+f"(d[1]), "+f"(d[2]), "+f"(d[3])
        : "r"(a[0]), "r"(a[1]), "r"(a[2]), "r"(a[3]), "r"(b[0]), "r"(b[1]));
}

// ---------------- small kernels ----------------
__global__ void zero_kernel(float* p, size_t n) {
    size_t i = (size_t)blockIdx.x * blockDim.x + threadIdx.x;
    size_t s = (size_t)gridDim.x * blockDim.x;
    for (; i < n; i += s) p[i] = 0.f;
}

template <int C>
__global__ void gn_stats(const float* __restrict__ x, int n, float* __restrict__ part) {
    const int CG = C / 4;
    const int RPB = 256 / CG;
    int tid = threadIdx.x;
    int cg = tid % CG;
    int rsub = tid / CG;
    float4 s = {0, 0, 0, 0}, q = {0, 0, 0, 0};
    for (long r = (long)blockIdx.x * RPB + rsub; r < n; r += (long)gridDim.x * RPB) {
        float4 v = *(const float4*)(x + r * C + cg * 4);
        s.x += v.x; s.y += v.y; s.z += v.z; s.w += v.w;
        q.x += v.x * v.x; q.y += v.y * v.y; q.z += v.z * v.z; q.w += v.w * v.w;
    }
    __shared__ float4 sh[256], sq[256];
    sh[tid] = s; sq[tid] = q;
    __syncthreads();
    if (rsub == 0) {
        for (int j = 1; j < RPB; j++) {
            float4 t = sh[j * CG + cg];
            s.x += t.x; s.y += t.y; s.z += t.z; s.w += t.w;
            t = sq[j * CG + cg];
            q.x += t.x; q.y += t.y; q.z += t.z; q.w += t.w;
        }
        *(float4*)&part[blockIdx.x * C + cg * 4] = s;
        *(float4*)&part[NB * C + blockIdx.x * C + cg * 4] = q;
    }
}

// fp16-input GN stats (C=256): 4 channels/thread, fp32 accumulation
template <int C>
__global__ void gn_stats_h(const fh* __restrict__ x, int n, float* __restrict__ part) {
    const int CG = C / 4;          // 64
    const int RPB = 256 / CG;      // 4
    int tid = threadIdx.x;
    int cg = tid % CG;
    int rsub = tid / CG;
    float4 s = {0, 0, 0, 0}, q = {0, 0, 0, 0};
    for (long r = (long)blockIdx.x * RPB + rsub; r < n; r += (long)gridDim.x * RPB) {
        uint2 raw = *(const uint2*)(x + r * C + cg * 4);
        float2 v01 = __half22float2(*(__half2*)&raw.x);
        float2 v23 = __half22float2(*(__half2*)&raw.y);
        s.x += v01.x; s.y += v01.y; s.z += v23.x; s.w += v23.y;
        q.x += v01.x * v01.x; q.y += v01.y * v01.y;
        q.z += v23.x * v23.x; q.w += v23.y * v23.y;
    }
    __shared__ float4 sh[256], sq[256];
    sh[tid] = s; sq[tid] = q;
    __syncthreads();
    if (rsub == 0) {
        for (int j = 1; j < RPB; j++) {
            float4 t = sh[j * CG + cg];
            s.x += t.x; s.y += t.y; s.z += t.z; s.w += t.w;
            t = sq[j * CG + cg];
            q.x += t.x; q.y += t.y; q.z += t.z; q.w += t.w;
        }
        *(float4*)&part[blockIdx.x * C + cg * 4] = s;
        *(float4*)&part[NB * C + blockIdx.x * C + cg * 4] = q;
    }
}

template <int C, int CPG>
__global__ void gn_finalize(const float* __restrict__ part, const float* __restrict__ w,
                            const float* __restrict__ b, float rcount) {
    int c = threadIdx.x;
    float s = 0.f, q = 0.f;
    for (int blk = 0; blk < NB; blk++) {
        s += part[blk * C + c];
        q += part[NB * C + blk * C + c];
    }
    __shared__ float cs[256], cq[256];
    cs[c] = s; cq[c] = q;
    __syncthreads();
    __shared__ float mu[32], rs[32];
    if (c < C / CPG) {
        float S = 0.f, Q = 0.f;
        for (int j = 0; j < CPG; j++) { S += cs[c * CPG + j]; Q += cq[c * CPG + j]; }
        float m = S * rcount;
        float v = Q * rcount - m * m;
        mu[c] = m;
        rs[c] = rsqrtf(v + 1e-5f);
    }
    __syncthreads();
    int g = c / CPG;
    float sc = w[c] * rs[g];
    g_scale[c] = sc;
    g_shift[c] = b[c] - mu[g] * sc;
}

__global__ void downsample_kernel(const float* __restrict__ feats,
                                  const int* __restrict__ seg, int n) {
    long t = (long)blockIdx.x * blockDim.x + threadIdx.x;
    if (t >= (long)n * 32) return;
    int row = (int)(t >> 5);
    int q = (int)(t & 31);
    int c = q * 4;
    int s = seg[row];
    float4 f = *(const float4*)(feats + (long)row * 128 + c);
    float4 sc = *(const float4*)(g_scale + c);
    float4 sh = *(const float4*)(g_shift + c);
    float h0 = silu_f(f.x * sc.x + sh.x);
    float h1 = silu_f(f.y * sc.y + sh.y);
    float h2 = silu_f(f.z * sc.z + sh.z);
    float h3 = silu_f(f.w * sc.w + sh.w);
    float* hp = g_A + (long)s * 128 + c;
    float* xp = g_B + (long)s * 128 + c;
    atomicAdd(hp + 0, h0); atomicAdd(hp + 1, h1);
    atomicAdd(hp + 2, h2); atomicAdd(hp + 3, h3);
    atomicAdd(xp + 0, f.x); atomicAdd(xp + 1, f.y);
    atomicAdd(xp + 2, f.z); atomicAdd(xp + 3, f.w);
    if (q == 0) atomicAdd(g_cnt + s, 1.f);
}

__global__ void finalize_down(int M) {
    long t = (long)blockIdx.x * blockDim.x + threadIdx.x;
    if (t >= (long)M * 32) return;
    int row = (int)(t >> 5);
    int c = (int)(t & 31) * 4;
    float ic = 1.f / fmaxf(g_cnt[row], 1.f);
    size_t base = (size_t)row * 128 + c;
    float4 va = *(const float4*)(g_A + base);
    float4 vb = *(const float4*)(g_B + base);
    g_hd[base + 0] = __float2half(va.x * ic);
    g_hd[base + 1] = __float2half(va.y * ic);
    g_hd[base + 2] = __float2half(va.z * ic);
    g_hd[base + 3] = __float2half(va.w * ic);
    g_xd[base + 0] = __float2half(vb.x * ic);
    g_xd[base + 1] = __float2half(vb.y * ic);
    g_xd[base + 2] = __float2half(vb.z * ic);
    g_xd[base + 3] = __float2half(vb.w * ic);
}

// GN2 apply + SiLU: fp16 h1 -> fp16 h2
__global__ void apply_gn2(int M) {
    long t = (long)blockIdx.x * blockDim.x + threadIdx.x;
    if (t >= (long)M * 64) return;
    int row = (int)(t >> 6);
    int c = (int)(t & 63) * 4;
    size_t base = (size_t)row * 256 + c;
    uint2 raw = *(const uint2*)(g_C + base);
    float2 v01 = __half22float2(*(__half2*)&raw.x);
    float2 v23 = __half22float2(*(__half2*)&raw.y);
    float4 sc = *(const float4*)(g_scale + c);
    float4 sh = *(const float4*)(g_shift + c);
    __half2 o01 = __floats2half2_rn(silu_f(v01.x * sc.x + sh.x),
                                    silu_f(v01.y * sc.y + sh.y));
    __half2 o23 = __floats2half2_rn(silu_f(v23.x * sc.z + sh.z),
                                    silu_f(v23.y * sc.w + sh.w));
    uint2 o;
    o.x = *(uint32_t*)&o01;
    o.y = *(uint32_t*)&o23;
    *(uint2*)(g_h2 + base) = o;
}

// transpose + fp16 + CHUNK/SWIZZLE for K=64 chunks, 128B rows:
// elt (k,c,n): ch=c>>6, kq=(c>>3)&7, o=c&7
// dst = ((k*NCH2+ch)*256 + n)*64 + ((kq ^ (n&7))<<3) + o
template <int CIN>
__global__ void prep_w(const float* __restrict__ W, fh* __restrict__ wo, int total) {
    int idx = blockIdx.x * blockDim.x + threadIdx.x;
    int stride = gridDim.x * blockDim.x;
    const int NCH2 = CIN / 64;
    for (; idx < total; idx += stride) {
        int c = idx % CIN;
        int n = (idx / CIN) % 256;
        int k = idx / (CIN * 256);
        float v = W[((size_t)k * CIN + c) * 256 + n];
        int ch = c >> 6, kq = (c >> 3) & 7, o = c & 7;
        size_t dst = ((size_t)(k * NCH2 + ch) * 256 + n) * 64 + ((kq ^ (n & 7)) << 3) + o;
        wo[dst] = __float2half(v);
    }
}

// ---------------- HMMA gather-conv: fp16, tile 128x128, K=64 chunks, occ 2 ------
// Grid = (M/128 tiles) x 2 N-halves. CTA 256 thr / 8 warps; warp grid 4(M)x2(N);
// warp tile 32x64. Chunks (tap, k0=64): A 128x64 fp16 cp.async (4 pieces/thread,
// zero-fill); B 128x64 fp16 via 1 bulk copy of the contiguous pre-swizzled slice.
// 128B rows, slot swizzle q^(row&7). 3 stages; half the chunk count of R11 ->
// half the per-chunk mbar/sync/issue overhead.
// SMEM: A 3x16KB @0, B 3x16KB @49152, mbars @98304, nid @98336 (28*128 ints).
static constexpr int CONV_SMEM = 98336 + 28 * 128 * 4;

template <int CIN, bool FUSE_SKIP, bool OUT_HALF>
__global__ __launch_bounds__(256, 2) void conv_hmma(
    const fh* __restrict__ x, const fh* __restrict__ w,
    const fh* __restrict__ sx, const fh* __restrict__ sw,
    const float* __restrict__ bias, const float* __restrict__ bias2,
    const int* __restrict__ nbr, void* __restrict__ outv, int M) {
    extern __shared__ char smem[];
    constexpr int NCH2 = CIN / 64;
    constexpr int NREG = 27 * NCH2;
    constexpr int TC = NREG + (FUSE_SKIP ? 2 : 0);
    constexpr int NT = FUSE_SKIP ? 28 : 27;
    const uint32_t sbase = smem_u32(smem);
    const uint32_t mbars = sbase + 98304;
    int* nid = (int*)(smem + 98336);
    const int tid = threadIdx.x;
    const int mbase = (blockIdx.x >> 1) * 128;
    const int n0 = (blockIdx.x & 1) * 128;
    const int lane = tid & 31;
    const int wm = (tid >> 5) >> 1;   // 0..3
    const int wn = (tid >> 5) & 1;    // 0..1

    if (tid == 0) {
        MBARRIER_INIT(mbars + 0, 1);
        MBARRIER_INIT(mbars + 8, 1);
        MBARRIER_INIT(mbars + 16, 1);
    }
    for (int u = tid; u < NT * 128; u += 256) {
        int tap = u >> 7;
        int r = mbase + (u & 127);
        nid[u] = (tap == 27) ? ((r < M) ? r : -1)
                             : ((r < M) ? nbr[(size_t)r * 27 + tap] : -1);
    }
    __syncthreads();

    float d[2][8][4];
#pragma unroll
    for (int a = 0; a < 2; a++)
#pragma unroll
        for (int b = 0; b < 8; b++)
#pragma unroll
            for (int c = 0; c < 4; c++) d[a][b][c] = 0.f;

    // issue chunk i: A via cp.async (1024 pieces, 4/thread); B via 1 bulk copy
    auto issueC = [&](int i) {
        int tap, c0, cin, ch;
        const fh *ax, *bw;
        if (i < NREG) {
            tap = i / NCH2; ch = i % NCH2; c0 = ch * 64; cin = CIN;
            ax = x;
            bw = w + (size_t)(tap * NCH2 + ch) * 16384 + n0 * 64;
        } else {
            tap = 27; ch = i - NREG; c0 = ch * 64; cin = 128;
            ax = sx;
            bw = sw + (size_t)ch * 16384 + n0 * 64;
        }
        const int* nt = nid + tap * 128;
        int st = i % 3;
        const uint32_t ab = sbase + st * 16384;
        const uint32_t bb = sbase + 49152 + st * 16384;
        if (tid == 0) {
            FENCE_ASYNC();
            MBAR_ARRIVE_EXPECT(mbars + st * 8, 16384u);
            cp_bulk_g2s(bb, bw, 16384u, mbars + st * 8);
        }
#pragma unroll
        for (int wv = 0; wv < 4; wv++) {
            int u = tid + wv * 256;
            int r = u >> 3, q = u & 7;
            int src = nt[r];
            const fh* sp = (src >= 0) ? (ax + (size_t)src * cin + c0 + q * 8)
                                      : (const fh*)g_zrow;
            cp_async16z(ab + r * 128 + ((q ^ (r & 7)) << 4),
                        sp, (src >= 0) ? 16u : 0u);
        }
        cp_commit();
    };

    issueC(0);
    if (TC > 1) issueC(1);

    for (int i = 0; i < TC; i++) {
        if (i < TC - 1) cp_wait1();
        else cp_wait0();
        int st = i % 3;
        MBARRIER_WAIT_PARITY(mbars + st * 8, (i / 3) & 1);
        __syncthreads();
        if (i + 2 < TC) issueC(i + 2);   // writes buf (i-1)%3: drained by sync

        const uint32_t ab = sbase + st * 16384;
        const uint32_t bb = sbase + 49152 + st * 16384;
#pragma unroll
        for (int ks = 0; ks < 4; ks++) {
            uint32_t ah[2][4];
            const int u = ks * 2 + ((lane >> 4) & 1);
#pragma unroll
            for (int mt = 0; mt < 2; mt++) {
                int row = wm * 32 + mt * 16 + (lane & 15);
                ldmx4(ah[mt], ab + row * 128 + ((u ^ (row & 7)) << 4));
            }
            const int brow = (lane & 7) + ((lane & 16) ? 8 : 0);
            const int bu = ks * 2 + ((lane >> 3) & 1);
#pragma unroll
            for (int p = 0; p < 4; p++) {
                int nl = wn * 64 + p * 16 + brow;   // local col in [0,128)
                uint32_t bh[4];
                ldmx4(bh, bb + nl * 128 + ((bu ^ (nl & 7)) << 4));
#pragma unroll
                for (int mt = 0; mt < 2; mt++) {
                    mma16816(d[mt][2 * p + 0], ah[mt], &bh[0]);
                    mma16816(d[mt][2 * p + 1], ah[mt], &bh[2]);
                }
            }
        }
    }

    // epilogue: direct global stores (fp32 out, or fp16 for conv1 -> g_C)
#pragma unroll
    for (int mt = 0; mt < 2; mt++) {
        int r0 = mbase + wm * 32 + mt * 16 + lane / 4;
#pragma unroll
        for (int t = 0; t < 8; t++) {
            int gc = n0 + wn * 64 + t * 8 + (lane % 4) * 2;
            float bx = bias[gc], by = bias[gc + 1];
            if (FUSE_SKIP) { bx += bias2[gc]; by += bias2[gc + 1]; }
            if (OUT_HALF) {
                fh* oh = (fh*)outv;
                if (r0 < M) {
                    __half2 v = __floats2half2_rn(d[mt][t][0] + bx, d[mt][t][1] + by);
                    *(__half2*)(oh + (size_t)r0 * 256 + gc) = v;
                }
                if (r0 + 8 < M) {
                    __half2 v = __floats2half2_rn(d[mt][t][2] + bx, d[mt][t][3] + by);
                    *(__half2*)(oh + (size_t)(r0 + 8) * 256 + gc) = v;
                }
            } else {
                float* of = (float*)outv;
                if (r0 < M) {
                    float2 v = {d[mt][t][0] + bx, d[mt][t][1] + by};
                    *(float2*)(of + (size_t)r0 * 256 + gc) = v;
                }
                if (r0 + 8 < M) {
                    float2 v = {d[mt][t][2] + bx, d[mt][t][3] + by};
                    *(float2*)(of + (size_t)(r0 + 8) * 256 + gc) = v;
                }
            }
        }
    }
}

// ---------------- launch ----------------
extern "C" void kernel_launch(void* const* d_in, const int* in_sizes, int n_in,
                              void* d_out, int out_size) {
    const float* feats = (const float*)d_in[0];
    const float* gn1_w = (const float*)d_in[1];
    const float* gn1_b = (const float*)d_in[2];
    const float* W1    = (const float*)d_in[3];
    const float* b1    = (const float*)d_in[4];
    const float* gn2_w = (const float*)d_in[5];
    const float* gn2_b = (const float*)d_in[6];
    const float* W2    = (const float*)d_in[7];
    const float* b2    = (const float*)d_in[8];
    const float* Wskip = (const float*)d_in[9];
    const float* bskip = (const float*)d_in[10];
    const int* pool_seg = (const int*)d_in[11];
    const int* nbr_idx  = (const int*)d_in[12];
    float* out = (float*)d_out;

    int N = in_sizes[0] / 128;
    int M = in_sizes[12] / 27;

    float *A, *B, *cnt, *part;
    cudaGetSymbolAddress((void**)&A, g_A);
    cudaGetSymbolAddress((void**)&B, g_B);
    cudaGetSymbolAddress((void**)&cnt, g_cnt);
    cudaGetSymbolAddress((void**)&part, g_part);
    fh *C, *hd, *xd, *h2, *W1p, *W2p, *WSp;
    cudaGetSymbolAddress((void**)&C, g_C);
    cudaGetSymbolAddress((void**)&hd, g_hd);
    cudaGetSymbolAddress((void**)&xd, g_xd);
    cudaGetSymbolAddress((void**)&h2, g_h2);
    cudaGetSymbolAddress((void**)&W1p, g_W1);
    cudaGetSymbolAddress((void**)&W2p, g_W2);
    cudaGetSymbolAddress((void**)&WSp, g_WS);

    cudaFuncSetAttribute(conv_hmma<128, false, true>,
                         cudaFuncAttributeMaxDynamicSharedMemorySize, CONV_SMEM);
    cudaFuncSetAttribute(conv_hmma<256, true, false>,
                         cudaFuncAttributeMaxDynamicSharedMemorySize, CONV_SMEM);

    // zero atomic accumulators (graph replays -> re-zero every launch)
    zero_kernel<<<4096, 256>>>(A, (size_t)M * 128);
    zero_kernel<<<4096, 256>>>(B, (size_t)M * 128);
    zero_kernel<<<256, 256>>>(cnt, (size_t)M);

    // weight transpose + fp16 + chunked/pre-swizzled layout (K=64 blocks)
    prep_w<128><<<1024, 256>>>(W1, W1p, 27 * 256 * 128);
    prep_w<256><<<2048, 256>>>(W2, W2p, 27 * 256 * 256);
    prep_w<128><<<128, 256>>>(Wskip, WSp, 256 * 128);

    // GN1 stats + finalize
    gn_stats<128><<<NB, 256>>>(feats, N, part);
    gn_finalize<128, 4><<<1, 128>>>(part, gn1_w, gn1_b, 1.f / ((float)N * 4.f));

    // GN1 apply + SiLU + segment sums; then means -> fp16 planes
    long dthreads = (long)N * 32;
    downsample_kernel<<<(int)((dthreads + 255) / 256), 256>>>(feats, pool_seg, N);
    long fthreads = (long)M * 32;
    finalize_down<<<(int)((fthreads + 255) / 256), 256>>>(M);

    int nconv = ((M + 127) / 128) * 2;   // x2 N-halves

    // conv1: h1 = conv(h_d, W1) + b1 (fp16 out)
    conv_hmma<128, false, true><<<nconv, 256, CONV_SMEM>>>(
        hd, W1p, nullptr, nullptr, b1, nullptr, nbr_idx, C, M);

    // GN2 stats (fp16 input) + finalize + apply (emits h2 fp16 plane)
    gn_stats_h<256><<<NB, 256>>>(C, M, part);
    gn_finalize<256, 8><<<1, 256>>>(part, gn2_w, gn2_b, 1.f / ((float)M * 8.f));
    long athreads = (long)M * 64;
    apply_gn2<<<(int)((athreads + 255) / 256), 256>>>(M);

    // conv2 + fused skip: out = conv(h2, W2) + b2 + x_d @ Wskip + bskip
    conv_hmma<256, true, false><<<nconv, 256, CONV_SMEM>>>(
        h2, W2p, xd, WSp, b2, bskip, nbr_idx, out, M);
}

// round 13
// speedup vs baseline: 1.3550x; 1.0258x over previous
#include <cuda_runtime.h>
#include <cuda_bf16.h>
#include <cuda_fp16.h>
#include <cstdint>

#define MMAX 200704
#define NB 512

typedef __half fh;

// ---------------- scratch (device globals; no allocation allowed) ----------------
__device__ float g_A[(size_t)MMAX * 128];   // h segment-sum accumulator
__device__ float g_B[(size_t)MMAX * 128];   // x segment-sum accumulator
__device__ fh    g_C[(size_t)MMAX * 256];   // h1 (conv1 out, fp16)
__device__ float g_cnt[MMAX];
__device__ float g_part[2 * NB * 256];
__device__ float g_scale[256];
__device__ float g_shift[256];
__device__ __align__(16) fh g_zrow[64];     // safe src for zero-fill cp.async
// fp16 operand planes (single plane each)
__device__ fh g_hd[(size_t)MMAX * 128];
__device__ fh g_xd[(size_t)MMAX * 128];
__device__ fh g_h2[(size_t)MMAX * 256];
// weights: chunked+pre-swizzled layout [tap*NCH2+ch][n=256][64] (fp16, 32KB blocks,
// 128B rows with slot swizzle q^(n&7))
__device__ __align__(16) fh g_W1[27 * 256 * 128];
__device__ __align__(16) fh g_W2[27 * 256 * 256];
__device__ __align__(16) fh g_WS[256 * 128];

__device__ __forceinline__ float silu_f(float x) { return x / (1.f + __expf(-x)); }

__device__ __forceinline__ uint32_t smem_u32(const void* p) {
    uint32_t a;
    asm("{ .reg .u64 t; cvta.to.shared.u64 t, %1; cvt.u32.u64 %0, t; }" : "=r"(a) : "l"(p));
    return a;
}
// zero-fill form: src-size=0 -> writes 16 zero bytes, NO global read issued
__device__ __forceinline__ void cp_async16z(uint32_t dst, const void* src, uint32_t srcsz) {
    asm volatile("cp.async.cg.shared.global [%0], [%1], 16, %2;"
                 :: "r"(dst), "l"(src), "r"(srcsz));
}
__device__ __forceinline__ void cp_commit() {
    asm volatile("cp.async.commit_group;" ::: "memory");
}
__device__ __forceinline__ void cp_wait0() { asm volatile("cp.async.wait_group 0;" ::: "memory"); }
__device__ __forceinline__ void cp_wait1() { asm volatile("cp.async.wait_group 1;" ::: "memory"); }
// bulk g2s copy completing on an mbarrier (sm_90 base feature)
__device__ __forceinline__ void cp_bulk_g2s(uint32_t dst, const void* src, uint32_t bytes,
                                            uint32_t mbar) {
    asm volatile(
        "cp.async.bulk.shared::cta.global.mbarrier::complete_tx::bytes [%0], [%1], %2, [%3];"
        :: "r"(dst), "l"(src), "r"(bytes), "r"(mbar) : "memory");
}
// vector reduction: 4 floats, one red op (sm_90+, PTX ISA 8.1)
__device__ __forceinline__ void red_add_v4(float* addr, float4 v) {
    asm volatile("red.global.add.v4.f32 [%0], {%1, %2, %3, %4};"
                 :: "l"(addr), "f"(v.x), "f"(v.y), "f"(v.z), "f"(v.w) : "memory");
}
#define MBARRIER_INIT(addr, cnt) \
    asm volatile("mbarrier.init.shared.b64 [%0], %1;" :: "r"(addr), "r"(cnt) : "memory")
#define MBAR_ARRIVE_EXPECT(m, b) \
    asm volatile("mbarrier.arrive.expect_tx.shared.b64 _, [%0], %1;" :: "r"(m), "r"(b) : "memory")
#define MBARRIER_WAIT_PARITY(addr, par) do {                                           \
    uint32_t _m = (addr); uint32_t _p = (par); uint32_t _done;                         \
    asm volatile("{\n\t.reg .pred p;\n\t"                                              \
        "mbarrier.try_wait.parity.acquire.cta.shared::cta.b64 p, [%1], %2;\n\t"        \
        "selp.b32 %0, 1, 0, p;\n\t}" : "=r"(_done) : "r"(_m), "r"(_p) : "memory");     \
    if (!_done) {                                                                      \
        asm volatile("{\n\t.reg .pred P1;\n\tWL_%=:\n\t"                               \
            "mbarrier.try_wait.parity.acquire.cta.shared::cta.b64 P1, [%0], %1, 0x989680;\n\t" \
            "@P1 bra.uni WD_%=;\n\tbra.uni WL_%=;\n\tWD_%=:\n\t}"                      \
            :: "r"(_m), "r"(_p) : "memory");                                           \
    } } while (0)
#define FENCE_ASYNC() asm volatile("fence.proxy.async.shared::cta;" ::: "memory")

__device__ __forceinline__ void ldmx4(uint32_t* r, uint32_t addr) {
    asm volatile("ldmatrix.sync.aligned.m8n8.x4.shared.b16 {%0,%1,%2,%3}, [%4];"
                 : "=r"(r[0]), "=r"(r[1]), "=r"(r[2]), "=r"(r[3]) : "r"(addr));
}
__device__ __forceinline__ void mma16816(float* d, const uint32_t* a, const uint32_t* b) {
    asm volatile(
        "mma.sync.aligned.m16n8k16.row.col.f32.f16.f16.f32 "
        "{%0,%1,%2,%3}, {%4,%5,%6,%7}, {%8,%9}, {%0,%1,%2,%3};"
        : "+f"(d[0]), "+f"(d[1]), "+f"(d[2]), "+f"(d[3])
        : "r"(a[0]), "r"(a[1]), "r"(a[2]), "r"(a[3]), "r"(b[0]), "r"(b[1]));
}

// ---------------- small kernels ----------------
// one launch zeroes g_A, g_B (M*128 each) and g_cnt (M)
__global__ void zero_all(float* a, float* b, float* cnt, size_t n128, int M) {
    size_t i = (size_t)blockIdx.x * blockDim.x + threadIdx.x;
    size_t s = (size_t)gridDim.x * blockDim.x;
    for (size_t j = i; j < n128; j += s) { a[j] = 0.f; b[j] = 0.f; }
    for (size_t j = i; j < (size_t)M; j += s) cnt[j] = 0.f;
}

template <int C>
__global__ void gn_stats(const float* __restrict__ x, int n, float* __restrict__ part) {
    const int CG = C / 4;
    const int RPB = 256 / CG;
    int tid = threadIdx.x;
    int cg = tid % CG;
    int rsub = tid / CG;
    float4 s = {0, 0, 0, 0}, q = {0, 0, 0, 0};
    for (long r = (long)blockIdx.x * RPB + rsub; r < n; r += (long)gridDim.x * RPB) {
        float4 v = *(const float4*)(x + r * C + cg * 4);
        s.x += v.x; s.y += v.y; s.z += v.z; s.w += v.w;
        q.x += v.x * v.x; q.y += v.y * v.y; q.z += v.z * v.z; q.w += v.w * v.w;
    }
    __shared__ float4 sh[256], sq[256];
    sh[tid] = s; sq[tid] = q;
    __syncthreads();
    if (rsub == 0) {
        for (int j = 1; j < RPB; j++) {
            float4 t = sh[j * CG + cg];
            s.x += t.x; s.y += t.y; s.z += t.z; s.w += t.w;
            t = sq[j * CG + cg];
            q.x += t.x; q.y += t.y; q.z += t.z; q.w += t.w;
        }
        *(float4*)&part[blockIdx.x * C + cg * 4] = s;
        *(float4*)&part[NB * C + blockIdx.x * C + cg * 4] = q;
    }
}

// fp16-input GN stats (C=256): 4 channels/thread, fp32 accumulation
template <int C>
__global__ void gn_stats_h(const fh* __restrict__ x, int n, float* __restrict__ part) {
    const int CG = C / 4;          // 64
    const int RPB = 256 / CG;      // 4
    int tid = threadIdx.x;
    int cg = tid % CG;
    int rsub = tid / CG;
    float4 s = {0, 0, 0, 0}, q = {0, 0, 0, 0};
    for (long r = (long)blockIdx.x * RPB + rsub; r < n; r += (long)gridDim.x * RPB) {
        uint2 raw = *(const uint2*)(x + r * C + cg * 4);
        float2 v01 = __half22float2(*(__half2*)&raw.x);
        float2 v23 = __half22float2(*(__half2*)&raw.y);
        s.x += v01.x; s.y += v01.y; s.z += v23.x; s.w += v23.y;
        q.x += v01.x * v01.x; q.y += v01.y * v01.y;
        q.z += v23.x * v23.x; q.w += v23.y * v23.y;
    }
    __shared__ float4 sh[256], sq[256];
    sh[tid] = s; sq[tid] = q;
    __syncthreads();
    if (rsub == 0) {
        for (int j = 1; j < RPB; j++) {
            float4 t = sh[j * CG + cg];
            s.x += t.x; s.y += t.y; s.z += t.z; s.w += t.w;
            t = sq[j * CG + cg];
            q.x += t.x; q.y += t.y; q.z += t.z; q.w += t.w;
        }
        *(float4*)&part[blockIdx.x * C + cg * 4] = s;
        *(float4*)&part[NB * C + blockIdx.x * C + cg * 4] = q;
    }
}

template <int C, int CPG>
__global__ void gn_finalize(const float* __restrict__ part, const float* __restrict__ w,
                            const float* __restrict__ b, float rcount) {
    int c = threadIdx.x;
    float s = 0.f, q = 0.f;
    for (int blk = 0; blk < NB; blk++) {
        s += part[blk * C + c];
        q += part[NB * C + blk * C + c];
    }
    __shared__ float cs[256], cq[256];
    cs[c] = s; cq[c] = q;
    __syncthreads();
    __shared__ float mu[32], rs[32];
    if (c < C / CPG) {
        float S = 0.f, Q = 0.f;
        for (int j = 0; j < CPG; j++) { S += cs[c * CPG + j]; Q += cq[c * CPG + j]; }
        float m = S * rcount;
        float v = Q * rcount - m * m;
        mu[c] = m;
        rs[c] = rsqrtf(v + 1e-5f);
    }
    __syncthreads();
    int g = c / CPG;
    float sc = w[c] * rs[g];
    g_scale[c] = sc;
    g_shift[c] = b[c] - mu[g] * sc;
}

__global__ void downsample_kernel(const float* __restrict__ feats,
                                  const int* __restrict__ seg, int n) {
    long t = (long)blockIdx.x * blockDim.x + threadIdx.x;
    if (t >= (long)n * 32) return;
    int row = (int)(t >> 5);
    int q = (int)(t & 31);
    int c = q * 4;
    int s = seg[row];
    float4 f = *(const float4*)(feats + (long)row * 128 + c);
    float4 sc = *(const float4*)(g_scale + c);
    float4 sh = *(const float4*)(g_shift + c);
    float4 h;
    h.x = silu_f(f.x * sc.x + sh.x);
    h.y = silu_f(f.y * sc.y + sh.y);
    h.z = silu_f(f.z * sc.z + sh.z);
    h.w = silu_f(f.w * sc.w + sh.w);
    red_add_v4(g_A + (long)s * 128 + c, h);
    red_add_v4(g_B + (long)s * 128 + c, f);
    if (q == 0) atomicAdd(g_cnt + s, 1.f);
}

__global__ void finalize_down(int M) {
    long t = (long)blockIdx.x * blockDim.x + threadIdx.x;
    if (t >= (long)M * 32) return;
    int row = (int)(t >> 5);
    int c = (int)(t & 31) * 4;
    float ic = 1.f / fmaxf(g_cnt[row], 1.f);
    size_t base = (size_t)row * 128 + c;
    float4 va = *(const float4*)(g_A + base);
    float4 vb = *(const float4*)(g_B + base);
    g_hd[base + 0] = __float2half(va.x * ic);
    g_hd[base + 1] = __float2half(va.y * ic);
    g_hd[base + 2] = __float2half(va.z * ic);
    g_hd[base + 3] = __float2half(va.w * ic);
    g_xd[base + 0] = __float2half(vb.x * ic);
    g_xd[base + 1] = __float2half(vb.y * ic);
    g_xd[base + 2] = __float2half(vb.z * ic);
    g_xd[base + 3] = __float2half(vb.w * ic);
}

// GN2 apply + SiLU: fp16 h1 -> fp16 h2
__global__ void apply_gn2(int M) {
    long t = (long)blockIdx.x * blockDim.x + threadIdx.x;
    if (t >= (long)M * 64) return;
    int row = (int)(t >> 6);
    int c = (int)(t & 63) * 4;
    size_t base = (size_t)row * 256 + c;
    uint2 raw = *(const uint2*)(g_C + base);
    float2 v01 = __half22float2(*(__half2*)&raw.x);
    float2 v23 = __half22float2(*(__half2*)&raw.y);
    float4 sc = *(const float4*)(g_scale + c);
    float4 sh = *(const float4*)(g_shift + c);
    __half2 o01 = __floats2half2_rn(silu_f(v01.x * sc.x + sh.x),
                                    silu_f(v01.y * sc.y + sh.y));
    __half2 o23 = __floats2half2_rn(silu_f(v23.x * sc.z + sh.z),
                                    silu_f(v23.y * sc.w + sh.w));
    uint2 o;
    o.x = *(uint32_t*)&o01;
    o.y = *(uint32_t*)&o23;
    *(uint2*)(g_h2 + base) = o;
}

// transpose + fp16 + CHUNK/SWIZZLE for K=64 chunks, 128B rows:
// elt (k,c,n): ch=c>>6, kq=(c>>3)&7, o=c&7
// dst = ((k*NCH2+ch)*256 + n)*64 + ((kq ^ (n&7))<<3) + o
template <int CIN>
__global__ void prep_w(const float* __restrict__ W, fh* __restrict__ wo, int total) {
    int idx = blockIdx.x * blockDim.x + threadIdx.x;
    int stride = gridDim.x * blockDim.x;
    const int NCH2 = CIN / 64;
    for (; idx < total; idx += stride) {
        int c = idx % CIN;
        int n = (idx / CIN) % 256;
        int k = idx / (CIN * 256);
        float v = W[((size_t)k * CIN + c) * 256 + n];
        int ch = c >> 6, kq = (c >> 3) & 7, o = c & 7;
        size_t dst = ((size_t)(k * NCH2 + ch) * 256 + n) * 64 + ((kq ^ (n & 7)) << 3) + o;
        wo[dst] = __float2half(v);
    }
}

// ---------------- HMMA gather-conv: fp16, tile 128x128, K=64 chunks, occ 2 ------
// Grid = (M/128 tiles) x 2 N-halves. CTA 256 thr / 8 warps; warp grid 4(M)x2(N);
// warp tile 32x64. Chunks (tap, k0=64): A 128x64 fp16 cp.async (4 pieces/thread,
// zero-fill); B 128x64 fp16 via 1 bulk copy of the contiguous pre-swizzled slice.
// 128B rows, slot swizzle q^(row&7). 3 stages, single __syncthreads per chunk.
// SMEM: A 3x16KB @0, B 3x16KB @49152, mbars @98304, nid @98336 (28*128 ints).
static constexpr int CONV_SMEM = 98336 + 28 * 128 * 4;

template <int CIN, bool FUSE_SKIP, bool OUT_HALF>
__global__ __launch_bounds__(256, 2) void conv_hmma(
    const fh* __restrict__ x, const fh* __restrict__ w,
    const fh* __restrict__ sx, const fh* __restrict__ sw,
    const float* __restrict__ bias, const float* __restrict__ bias2,
    const int* __restrict__ nbr, void* __restrict__ outv, int M) {
    extern __shared__ char smem[];
    constexpr int NCH2 = CIN / 64;
    constexpr int NREG = 27 * NCH2;
    constexpr int TC = NREG + (FUSE_SKIP ? 2 : 0);
    constexpr int NT = FUSE_SKIP ? 28 : 27;
    const uint32_t sbase = smem_u32(smem);
    const uint32_t mbars = sbase + 98304;
    int* nid = (int*)(smem + 98336);
    const int tid = threadIdx.x;
    const int mbase = (blockIdx.x >> 1) * 128;
    const int n0 = (blockIdx.x & 1) * 128;
    const int lane = tid & 31;
    const int wm = (tid >> 5) >> 1;   // 0..3
    const int wn = (tid >> 5) & 1;    // 0..1

    if (tid == 0) {
        MBARRIER_INIT(mbars + 0, 1);
        MBARRIER_INIT(mbars + 8, 1);
        MBARRIER_INIT(mbars + 16, 1);
    }
    for (int u = tid; u < NT * 128; u += 256) {
        int tap = u >> 7;
        int r = mbase + (u & 127);
        nid[u] = (tap == 27) ? ((r < M) ? r : -1)
                             : ((r < M) ? nbr[(size_t)r * 27 + tap] : -1);
    }
    __syncthreads();

    float d[2][8][4];
#pragma unroll
    for (int a = 0; a < 2; a++)
#pragma unroll
        for (int b = 0; b < 8; b++)
#pragma unroll
            for (int c = 0; c < 4; c++) d[a][b][c] = 0.f;

    // issue chunk i: A via cp.async (1024 pieces, 4/thread); B via 1 bulk copy
    auto issueC = [&](int i) {
        int tap, c0, cin, ch;
        const fh *ax, *bw;
        if (i < NREG) {
            tap = i / NCH2; ch = i % NCH2; c0 = ch * 64; cin = CIN;
            ax = x;
            bw = w + (size_t)(tap * NCH2 + ch) * 16384 + n0 * 64;
        } else {
            tap = 27; ch = i - NREG; c0 = ch * 64; cin = 128;
            ax = sx;
            bw = sw + (size_t)ch * 16384 + n0 * 64;
        }
        const int* nt = nid + tap * 128;
        int st = i % 3;
        const uint32_t ab = sbase + st * 16384;
        const uint32_t bb = sbase + 49152 + st * 16384;
        if (tid == 0) {
            FENCE_ASYNC();
            MBAR_ARRIVE_EXPECT(mbars + st * 8, 16384u);
            cp_bulk_g2s(bb, bw, 16384u, mbars + st * 8);
        }
#pragma unroll
        for (int wv = 0; wv < 4; wv++) {
            int u = tid + wv * 256;
            int r = u >> 3, q = u & 7;
            int src = nt[r];
            const fh* sp = (src >= 0) ? (ax + (size_t)src * cin + c0 + q * 8)
                                      : (const fh*)g_zrow;
            cp_async16z(ab + r * 128 + ((q ^ (r & 7)) << 4),
                        sp, (src >= 0) ? 16u : 0u);
        }
        cp_commit();
    };

    issueC(0);
    if (TC > 1) issueC(1);

    for (int i = 0; i < TC; i++) {
        if (i < TC - 1) cp_wait1();
        else cp_wait0();
        int st = i % 3;
        MBARRIER_WAIT_PARITY(mbars + st * 8, (i / 3) & 1);
        __syncthreads();
        if (i + 2 < TC) issueC(i + 2);   // writes buf (i-1)%3: drained by sync

        const uint32_t ab = sbase + st * 16384;
        const uint32_t bb = sbase + 49152 + st * 16384;
#pragma unroll
        for (int ks = 0; ks < 4; ks++) {
            uint32_t ah[2][4];
            const int u = ks * 2 + ((lane >> 4) & 1);
#pragma unroll
            for (int mt = 0; mt < 2; mt++) {
                int row = wm * 32 + mt * 16 + (lane & 15);
                ldmx4(ah[mt], ab + row * 128 + ((u ^ (row & 7)) << 4));
            }
            const int brow = (lane & 7) + ((lane & 16) ? 8 : 0);
            const int bu = ks * 2 + ((lane >> 3) & 1);
#pragma unroll
            for (int p = 0; p < 4; p++) {
                int nl = wn * 64 + p * 16 + brow;   // local col in [0,128)
                uint32_t bh[4];
                ldmx4(bh, bb + nl * 128 + ((bu ^ (nl & 7)) << 4));
#pragma unroll
                for (int mt = 0; mt < 2; mt++) {
                    mma16816(d[mt][2 * p + 0], ah[mt], &bh[0]);
                    mma16816(d[mt][2 * p + 1], ah[mt], &bh[2]);
                }
            }
        }
    }

    // epilogue: direct global stores (fp32 out, or fp16 for conv1 -> g_C)
#pragma unroll
    for (int mt = 0; mt < 2; mt++) {
        int r0 = mbase + wm * 32 + mt * 16 + lane / 4;
#pragma unroll
        for (int t = 0; t < 8; t++) {
            int gc = n0 + wn * 64 + t * 8 + (lane % 4) * 2;
            float bx = bias[gc], by = bias[gc + 1];
            if (FUSE_SKIP) { bx += bias2[gc]; by += bias2[gc + 1]; }
            if (OUT_HALF) {
                fh* oh = (fh*)outv;
                if (r0 < M) {
                    __half2 v = __floats2half2_rn(d[mt][t][0] + bx, d[mt][t][1] + by);
                    *(__half2*)(oh + (size_t)r0 * 256 + gc) = v;
                }
                if (r0 + 8 < M) {
                    __half2 v = __floats2half2_rn(d[mt][t][2] + bx, d[mt][t][3] + by);
                    *(__half2*)(oh + (size_t)(r0 + 8) * 256 + gc) = v;
                }
            } else {
                float* of = (float*)outv;
                if (r0 < M) {
                    float2 v = {d[mt][t][0] + bx, d[mt][t][1] + by};
                    *(float2*)(of + (size_t)r0 * 256 + gc) = v;
                }
                if (r0 + 8 < M) {
                    float2 v = {d[mt][t][2] + bx, d[mt][t][3] + by};
                    *(float2*)(of + (size_t)(r0 + 8) * 256 + gc) = v;
                }
            }
        }
    }
}

// ---------------- launch ----------------
extern "C" void kernel_launch(void* const* d_in, const int* in_sizes, int n_in,
                              void* d_out, int out_size) {
    const float* feats = (const float*)d_in[0];
    const float* gn1_w = (const float*)d_in[1];
    const float* gn1_b = (const float*)d_in[2];
    const float* W1    = (const float*)d_in[3];
    const float* b1    = (const float*)d_in[4];
    const float* gn2_w = (const float*)d_in[5];
    const float* gn2_b = (const float*)d_in[6];
    const float* W2    = (const float*)d_in[7];
    const float* b2    = (const float*)d_in[8];
    const float* Wskip = (const float*)d_in[9];
    const float* bskip = (const float*)d_in[10];
    const int* pool_seg = (const int*)d_in[11];
    const int* nbr_idx  = (const int*)d_in[12];
    float* out = (float*)d_out;

    int N = in_sizes[0] / 128;
    int M = in_sizes[12] / 27;

    float *A, *B, *cnt, *part;
    cudaGetSymbolAddress((void**)&A, g_A);
    cudaGetSymbolAddress((void**)&B, g_B);
    cudaGetSymbolAddress((void**)&cnt, g_cnt);
    cudaGetSymbolAddress((void**)&part, g_part);
    fh *C, *hd, *xd, *h2, *W1p, *W2p, *WSp;
    cudaGetSymbolAddress((void**)&C, g_C);
    cudaGetSymbolAddress((void**)&hd, g_hd);
    cudaGetSymbolAddress((void**)&xd, g_xd);
    cudaGetSymbolAddress((void**)&h2, g_h2);
    cudaGetSymbolAddress((void**)&W1p, g_W1);
    cudaGetSymbolAddress((void**)&W2p, g_W2);
    cudaGetSymbolAddress((void**)&WSp, g_WS);

    cudaFuncSetAttribute(conv_hmma<128, false, true>,
                         cudaFuncAttributeMaxDynamicSharedMemorySize, CONV_SMEM);
    cudaFuncSetAttribute(conv_hmma<256, true, false>,
                         cudaFuncAttributeMaxDynamicSharedMemorySize, CONV_SMEM);

    // zero atomic accumulators (graph replays -> re-zero every launch)
    zero_all<<<4096, 256>>>(A, B, cnt, (size_t)M * 128, M);

    // weight transpose + fp16 + chunked/pre-swizzled layout (K=64 blocks)
    prep_w<128><<<1024, 256>>>(W1, W1p, 27 * 256 * 128);
    prep_w<256><<<2048, 256>>>(W2, W2p, 27 * 256 * 256);
    prep_w<128><<<128, 256>>>(Wskip, WSp, 256 * 128);

    // GN1 stats + finalize
    gn_stats<128><<<NB, 256>>>(feats, N, part);
    gn_finalize<128, 4><<<1, 128>>>(part, gn1_w, gn1_b, 1.f / ((float)N * 4.f));

    // GN1 apply + SiLU + segment sums (vector red); then means -> fp16 planes
    long dthreads = (long)N * 32;
    downsample_kernel<<<(int)((dthreads + 255) / 256), 256>>>(feats, pool_seg, N);
    long fthreads = (long)M * 32;
    finalize_down<<<(int)((fthreads + 255) / 256), 256>>>(M);

    int nconv = ((M + 127) / 128) * 2;   // x2 N-halves

    // conv1: h1 = conv(h_d, W1) + b1 (fp16 out)
    conv_hmma<128, false, true><<<nconv, 256, CONV_SMEM>>>(
        hd, W1p, nullptr, nullptr, b1, nullptr, nbr_idx, C, M);

    // GN2 stats (fp16 input) + finalize + apply (emits h2 fp16 plane)
    gn_stats_h<256><<<NB, 256>>>(C, M, part);
    gn_finalize<256, 8><<<1, 256>>>(part, gn2_w, gn2_b, 1.f / ((float)M * 8.f));
    long athreads = (long)M * 64;
    apply_gn2<<<(int)((athreads + 255) / 256), 256>>>(M);

    // conv2 + fused skip: out = conv(h2, W2) + b2 + x_d @ Wskip + bskip
    conv_hmma<256, true, false><<<nconv, 256, CONV_SMEM>>>(
        h2, W2p, xd, WSp, b2, bskip, nbr_idx, out, M);
}

// round 14
// speedup vs baseline: 1.3611x; 1.0045x over previous
#include <cuda_runtime.h>
#include <cuda_bf16.h>
#include <cuda_fp16.h>
#include <cstdint>

#define MMAX 200704
#define NB 512

typedef __half fh;

// ---------------- scratch (device globals; no allocation allowed) ----------------
__device__ float g_A[(size_t)MMAX * 128];   // h segment-sum accumulator
__device__ float g_B[(size_t)MMAX * 128];   // x segment-sum accumulator
__device__ fh    g_C[(size_t)MMAX * 256];   // h1 (conv1 out, fp16)
__device__ float g_cnt[MMAX];
__device__ float g_part[2 * NB * 256];
__device__ float g_scale[256];
__device__ float g_shift[256];
__device__ __align__(16) fh g_zrow[64];     // safe src for zero-fill cp.async
// fp16 operand planes (single plane each)
__device__ fh g_hd[(size_t)MMAX * 128];
__device__ fh g_xd[(size_t)MMAX * 128];
__device__ fh g_h2[(size_t)MMAX * 256];
// weights: chunked+pre-swizzled layout [tap*NCH2+ch][n=256][64] (fp16, 32KB blocks,
// 128B rows with slot swizzle q^(n&7))
__device__ __align__(16) fh g_W1[27 * 256 * 128];
__device__ __align__(16) fh g_W2[27 * 256 * 256];
__device__ __align__(16) fh g_WS[256 * 128];

__device__ __forceinline__ float silu_f(float x) { return x / (1.f + __expf(-x)); }

// PDL: wait for previous grid's implicit completion trigger (acquire semantics)
__device__ __forceinline__ void gdc_wait() {
    asm volatile("griddepcontrol.wait;" ::: "memory");
}

__device__ __forceinline__ uint32_t smem_u32(const void* p) {
    uint32_t a;
    asm("{ .reg .u64 t; cvta.to.shared.u64 t, %1; cvt.u32.u64 %0, t; }" : "=r"(a) : "l"(p));
    return a;
}
// zero-fill form: src-size=0 -> writes 16 zero bytes, NO global read issued
__device__ __forceinline__ void cp_async16z(uint32_t dst, const void* src, uint32_t srcsz) {
    asm volatile("cp.async.cg.shared.global [%0], [%1], 16, %2;"
                 :: "r"(dst), "l"(src), "r"(srcsz));
}
__device__ __forceinline__ void cp_commit() {
    asm volatile("cp.async.commit_group;" ::: "memory");
}
__device__ __forceinline__ void cp_wait0() { asm volatile("cp.async.wait_group 0;" ::: "memory"); }
__device__ __forceinline__ void cp_wait1() { asm volatile("cp.async.wait_group 1;" ::: "memory"); }
// bulk g2s copy completing on an mbarrier (sm_90 base feature)
__device__ __forceinline__ void cp_bulk_g2s(uint32_t dst, const void* src, uint32_t bytes,
                                            uint32_t mbar) {
    asm volatile(
        "cp.async.bulk.shared::cta.global.mbarrier::complete_tx::bytes [%0], [%1], %2, [%3];"
        :: "r"(dst), "l"(src), "r"(bytes), "r"(mbar) : "memory");
}
// vector reduction: 4 floats, one red op (sm_90+, PTX ISA 8.1)
__device__ __forceinline__ void red_add_v4(float* addr, float4 v) {
    asm volatile("red.global.add.v4.f32 [%0], {%1, %2, %3, %4};"
                 :: "l"(addr), "f"(v.x), "f"(v.y), "f"(v.z), "f"(v.w) : "memory");
}
#define MBARRIER_INIT(addr, cnt) \
    asm volatile("mbarrier.init.shared.b64 [%0], %1;" :: "r"(addr), "r"(cnt) : "memory")
#define MBAR_ARRIVE_EXPECT(m, b) \
    asm volatile("mbarrier.arrive.expect_tx.shared.b64 _, [%0], %1;" :: "r"(m), "r"(b) : "memory")
#define MBARRIER_WAIT_PARITY(addr, par) do {                                           \
    uint32_t _m = (addr); uint32_t _p = (par); uint32_t _done;                         \
    asm volatile("{\n\t.reg .pred p;\n\t"                                              \
        "mbarrier.try_wait.parity.acquire.cta.shared::cta.b64 p, [%1], %2;\n\t"        \
        "selp.b32 %0, 1, 0, p;\n\t}" : "=r"(_done) : "r"(_m), "r"(_p) : "memory");     \
    if (!_done) {                                                                      \
        asm volatile("{\n\t.reg .pred P1;\n\tWL_%=:\n\t"                               \
            "mbarrier.try_wait.parity.acquire.cta.shared::cta.b64 P1, [%0], %1, 0x989680;\n\t" \
            "@P1 bra.uni WD_%=;\n\tbra.uni WL_%=;\n\tWD_%=:\n\t}"                      \
            :: "r"(_m), "r"(_p) : "memory");                                           \
    } } while (0)
#define FENCE_ASYNC() asm volatile("fence.proxy.async.shared::cta;" ::: "memory")

__device__ __forceinline__ void ldmx4(uint32_t* r, uint32_t addr) {
    asm volatile("ldmatrix.sync.aligned.m8n8.x4.shared.b16 {%0,%1,%2,%3}, [%4];"
                 : "=r"(r[0]), "=r"(r[1]), "=r"(r[2]), "=r"(r[3]) : "r"(addr));
}
__device__ __forceinline__ void mma16816(float* d, const uint32_t* a, const uint32_t* b) {
    asm volatile(
        "mma.sync.aligned.m16n8k16.row.col.f32.f16.f16.f32 "
        "{%0,%1,%2,%3}, {%4,%5,%6,%7}, {%8,%9}, {%0,%1,%2,%3};"
        : "+f"(d[0]), "+f"(d[1]), "+f"(d[2]), "+f"(d[3])
        : "r"(a[0]), "r"(a[1]), "r"(a[2]), "r"(a[3]), "r"(b[0]), "r"(b[1]));
}

// ---------------- small kernels ----------------
// one launch zeroes g_A, g_B (M*128 each) and g_cnt (M)
__global__ void zero_all(float* a, float* b, float* cnt, size_t n128, int M) {
    size_t i = (size_t)blockIdx.x * blockDim.x + threadIdx.x;
    size_t s = (size_t)gridDim.x * blockDim.x;
    for (size_t j = i; j < n128; j += s) { a[j] = 0.f; b[j] = 0.f; }
    for (size_t j = i; j < (size_t)M; j += s) cnt[j] = 0.f;
}

// single prep kernel: transpose + fp16 + chunk/swizzle all three weight tensors.
// layout per tensor: elt (k,c,n): ch=c>>6, kq=(c>>3)&7, o=c&7
// dst = ((k*NCH2+ch)*256 + n)*64 + ((kq ^ (n&7))<<3) + o
__global__ void prep_all(const float* __restrict__ W1, const float* __restrict__ W2,
                         const float* __restrict__ WS) {
    const int T1 = 27 * 256 * 128;
    const int T2 = 27 * 256 * 256;
    const int T3 = 256 * 128;
    const int total = T1 + T2 + T3;
    int idx = blockIdx.x * blockDim.x + threadIdx.x;
    int stride = gridDim.x * blockDim.x;
    for (; idx < total; idx += stride) {
        const float* W;
        fh* wo;
        int rem, cin;
        if (idx < T1) { W = W1; wo = g_W1; rem = idx; cin = 128; }
        else if (idx < T1 + T2) { W = W2; wo = g_W2; rem = idx - T1; cin = 256; }
        else { W = WS; wo = g_WS; rem = idx - T1 - T2; cin = 128; }
        int c = rem % cin;
        int n = (rem / cin) % 256;
        int k = rem / (cin * 256);
        float v = W[((size_t)k * cin + c) * 256 + n];
        int NCH2 = cin / 64;
        int ch = c >> 6, kq = (c >> 3) & 7, o = c & 7;
        size_t dst = ((size_t)(k * NCH2 + ch) * 256 + n) * 64 + ((kq ^ (n & 7)) << 3) + o;
        wo[dst] = __float2half(v);
    }
}

template <int C>
__global__ void gn_stats(const float* __restrict__ x, int n, float* __restrict__ part) {
    gdc_wait();
    const int CG = C / 4;
    const int RPB = 256 / CG;
    int tid = threadIdx.x;
    int cg = tid % CG;
    int rsub = tid / CG;
    float4 s = {0, 0, 0, 0}, q = {0, 0, 0, 0};
    for (long r = (long)blockIdx.x * RPB + rsub; r < n; r += (long)gridDim.x * RPB) {
        float4 v = *(const float4*)(x + r * C + cg * 4);
        s.x += v.x; s.y += v.y; s.z += v.z; s.w += v.w;
        q.x += v.x * v.x; q.y += v.y * v.y; q.z += v.z * v.z; q.w += v.w * v.w;
    }
    __shared__ float4 sh[256], sq[256];
    sh[tid] = s; sq[tid] = q;
    __syncthreads();
    if (rsub == 0) {
        for (int j = 1; j < RPB; j++) {
            float4 t = sh[j * CG + cg];
            s.x += t.x; s.y += t.y; s.z += t.z; s.w += t.w;
            t = sq[j * CG + cg];
            q.x += t.x; q.y += t.y; q.z += t.z; q.w += t.w;
        }
        *(float4*)&part[blockIdx.x * C + cg * 4] = s;
        *(float4*)&part[NB * C + blockIdx.x * C + cg * 4] = q;
    }
}

// fp16-input GN stats (C=256)
template <int C>
__global__ void gn_stats_h(const fh* __restrict__ x, int n, float* __restrict__ part) {
    gdc_wait();
    const int CG = C / 4;
    const int RPB = 256 / CG;
    int tid = threadIdx.x;
    int cg = tid % CG;
    int rsub = tid / CG;
    float4 s = {0, 0, 0, 0}, q = {0, 0, 0, 0};
    for (long r = (long)blockIdx.x * RPB + rsub; r < n; r += (long)gridDim.x * RPB) {
        uint2 raw = *(const uint2*)(x + r * C + cg * 4);
        float2 v01 = __half22float2(*(__half2*)&raw.x);
        float2 v23 = __half22float2(*(__half2*)&raw.y);
        s.x += v01.x; s.y += v01.y; s.z += v23.x; s.w += v23.y;
        q.x += v01.x * v01.x; q.y += v01.y * v01.y;
        q.z += v23.x * v23.x; q.w += v23.y * v23.y;
    }
    __shared__ float4 sh[256], sq[256];
    sh[tid] = s; sq[tid] = q;
    __syncthreads();
    if (rsub == 0) {
        for (int j = 1; j < RPB; j++) {
            float4 t = sh[j * CG + cg];
            s.x += t.x; s.y += t.y; s.z += t.z; s.w += t.w;
            t = sq[j * CG + cg];
            q.x += t.x; q.y += t.y; q.z += t.z; q.w += t.w;
        }
        *(float4*)&part[blockIdx.x * C + cg * 4] = s;
        *(float4*)&part[NB * C + blockIdx.x * C + cg * 4] = q;
    }
}

template <int C, int CPG>
__global__ void gn_finalize(const float* __restrict__ part, const float* __restrict__ w,
                            const float* __restrict__ b, float rcount) {
    gdc_wait();
    int c = threadIdx.x;
    float s = 0.f, q = 0.f;
    for (int blk = 0; blk < NB; blk++) {
        s += part[blk * C + c];
        q += part[NB * C + blk * C + c];
    }
    __shared__ float cs[256], cq[256];
    cs[c] = s; cq[c] = q;
    __syncthreads();
    __shared__ float mu[32], rs[32];
    if (c < C / CPG) {
        float S = 0.f, Q = 0.f;
        for (int j = 0; j < CPG; j++) { S += cs[c * CPG + j]; Q += cq[c * CPG + j]; }
        float m = S * rcount;
        float v = Q * rcount - m * m;
        mu[c] = m;
        rs[c] = rsqrtf(v + 1e-5f);
    }
    __syncthreads();
    int g = c / CPG;
    float sc = w[c] * rs[g];
    g_scale[c] = sc;
    g_shift[c] = b[c] - mu[g] * sc;
}

__global__ void downsample_kernel(const float* __restrict__ feats,
                                  const int* __restrict__ seg, int n) {
    long t = (long)blockIdx.x * blockDim.x + threadIdx.x;
    if (t >= (long)n * 32) { gdc_wait(); return; }
    int row = (int)(t >> 5);
    int q = (int)(t & 31);
    int c = q * 4;
    int s = seg[row];                                  // harness input: safe pre-wait
    float4 f = *(const float4*)(feats + (long)row * 128 + c);
    gdc_wait();                                        // g_scale/g_shift + zeroed bufs
    float4 sc = *(const float4*)(g_scale + c);
    float4 sh = *(const float4*)(g_shift + c);
    float4 h;
    h.x = silu_f(f.x * sc.x + sh.x);
    h.y = silu_f(f.y * sc.y + sh.y);
    h.z = silu_f(f.z * sc.z + sh.z);
    h.w = silu_f(f.w * sc.w + sh.w);
    red_add_v4(g_A + (long)s * 128 + c, h);
    red_add_v4(g_B + (long)s * 128 + c, f);
    if (q == 0) atomicAdd(g_cnt + s, 1.f);
}

__global__ void finalize_down(int M) {
    gdc_wait();
    long t = (long)blockIdx.x * blockDim.x + threadIdx.x;
    if (t >= (long)M * 32) return;
    int row = (int)(t >> 5);
    int c = (int)(t & 31) * 4;
    float ic = 1.f / fmaxf(g_cnt[row], 1.f);
    size_t base = (size_t)row * 128 + c;
    float4 va = *(const float4*)(g_A + base);
    float4 vb = *(const float4*)(g_B + base);
    g_hd[base + 0] = __float2half(va.x * ic);
    g_hd[base + 1] = __float2half(va.y * ic);
    g_hd[base + 2] = __float2half(va.z * ic);
    g_hd[base + 3] = __float2half(va.w * ic);
    g_xd[base + 0] = __float2half(vb.x * ic);
    g_xd[base + 1] = __float2half(vb.y * ic);
    g_xd[base + 2] = __float2half(vb.z * ic);
    g_xd[base + 3] = __float2half(vb.w * ic);
}

// GN2 apply + SiLU: fp16 h1 -> fp16 h2
__global__ void apply_gn2(int M) {
    gdc_wait();
    long t = (long)blockIdx.x * blockDim.x + threadIdx.x;
    if (t >= (long)M * 64) return;
    int row = (int)(t >> 6);
    int c = (int)(t & 63) * 4;
    size_t base = (size_t)row * 256 + c;
    uint2 raw = *(const uint2*)(g_C + base);
    float2 v01 = __half22float2(*(__half2*)&raw.x);
    float2 v23 = __half22float2(*(__half2*)&raw.y);
    float4 sc = *(const float4*)(g_scale + c);
    float4 sh = *(const float4*)(g_shift + c);
    __half2 o01 = __floats2half2_rn(silu_f(v01.x * sc.x + sh.x),
                                    silu_f(v01.y * sc.y + sh.y));
    __half2 o23 = __floats2half2_rn(silu_f(v23.x * sc.z + sh.z),
                                    silu_f(v23.y * sc.w + sh.w));
    uint2 o;
    o.x = *(uint32_t*)&o01;
    o.y = *(uint32_t*)&o23;
    *(uint2*)(g_h2 + base) = o;
}

// ---------------- HMMA gather-conv: fp16, tile 128x128, K=64 chunks, occ 2 ------
// Grid = (M/128 tiles) x 2 N-halves. CTA 256 thr / 8 warps; warp grid 4(M)x2(N);
// warp tile 32x64. Chunks (tap, k0=64): A 128x64 fp16 cp.async (4 pieces/thread,
// zero-fill); B 128x64 fp16 via 1 bulk copy of the contiguous pre-swizzled slice.
// 128B rows, slot swizzle q^(row&7). 3 stages, single __syncthreads per chunk.
// PDL: mbar-init + nid prefetch (harness inputs only) run BEFORE griddep wait.
// SMEM: A 3x16KB @0, B 3x16KB @49152, mbars @98304, nid @98336 (28*128 ints).
static constexpr int CONV_SMEM = 98336 + 28 * 128 * 4;

template <int CIN, bool FUSE_SKIP, bool OUT_HALF>
__global__ __launch_bounds__(256, 2) void conv_hmma(
    const fh* __restrict__ x, const fh* __restrict__ w,
    const fh* __restrict__ sx, const fh* __restrict__ sw,
    const float* __restrict__ bias, const float* __restrict__ bias2,
    const int* __restrict__ nbr, void* __restrict__ outv, int M) {
    extern __shared__ char smem[];
    constexpr int NCH2 = CIN / 64;
    constexpr int NREG = 27 * NCH2;
    constexpr int TC = NREG + (FUSE_SKIP ? 2 : 0);
    constexpr int NT = FUSE_SKIP ? 28 : 27;
    const uint32_t sbase = smem_u32(smem);
    const uint32_t mbars = sbase + 98304;
    int* nid = (int*)(smem + 98336);
    const int tid = threadIdx.x;
    const int mbase = (blockIdx.x >> 1) * 128;
    const int n0 = (blockIdx.x & 1) * 128;
    const int lane = tid & 31;
    const int wm = (tid >> 5) >> 1;   // 0..3
    const int wn = (tid >> 5) & 1;    // 0..1

    // prologue independent of predecessor output (nbr is a harness input)
    if (tid == 0) {
        MBARRIER_INIT(mbars + 0, 1);
        MBARRIER_INIT(mbars + 8, 1);
        MBARRIER_INIT(mbars + 16, 1);
    }
    for (int u = tid; u < NT * 128; u += 256) {
        int tap = u >> 7;
        int r = mbase + (u & 127);
        nid[u] = (tap == 27) ? ((r < M) ? r : -1)
                             : ((r < M) ? nbr[(size_t)r * 27 + tap] : -1);
    }
    __syncthreads();
    gdc_wait();   // operands (planes/weights) produced by predecessor grids

    float d[2][8][4];
#pragma unroll
    for (int a = 0; a < 2; a++)
#pragma unroll
        for (int b = 0; b < 8; b++)
#pragma unroll
            for (int c = 0; c < 4; c++) d[a][b][c] = 0.f;

    // issue chunk i: A via cp.async (1024 pieces, 4/thread); B via 1 bulk copy
    auto issueC = [&](int i) {
        int tap, c0, cin, ch;
        const fh *ax, *bw;
        if (i < NREG) {
            tap = i / NCH2; ch = i % NCH2; c0 = ch * 64; cin = CIN;
            ax = x;
            bw = w + (size_t)(tap * NCH2 + ch) * 16384 + n0 * 64;
        } else {
            tap = 27; ch = i - NREG; c0 = ch * 64; cin = 128;
            ax = sx;
            bw = sw + (size_t)ch * 16384 + n0 * 64;
        }
        const int* nt = nid + tap * 128;
        int st = i % 3;
        const uint32_t ab = sbase + st * 16384;
        const uint32_t bb = sbase + 49152 + st * 16384;
        if (tid == 0) {
            FENCE_ASYNC();
            MBAR_ARRIVE_EXPECT(mbars + st * 8, 16384u);
            cp_bulk_g2s(bb, bw, 16384u, mbars + st * 8);
        }
#pragma unroll
        for (int wv = 0; wv < 4; wv++) {
            int u = tid + wv * 256;
            int r = u >> 3, q = u & 7;
            int src = nt[r];
            const fh* sp = (src >= 0) ? (ax + (size_t)src * cin + c0 + q * 8)
                                      : (const fh*)g_zrow;
            cp_async16z(ab + r * 128 + ((q ^ (r & 7)) << 4),
                        sp, (src >= 0) ? 16u : 0u);
        }
        cp_commit();
    };

    issueC(0);
    if (TC > 1) issueC(1);

    for (int i = 0; i < TC; i++) {
        if (i < TC - 1) cp_wait1();
        else cp_wait0();
        int st = i % 3;
        MBARRIER_WAIT_PARITY(mbars + st * 8, (i / 3) & 1);
        __syncthreads();
        if (i + 2 < TC) issueC(i + 2);   // writes buf (i-1)%3: drained by sync

        const uint32_t ab = sbase + st * 16384;
        const uint32_t bb = sbase + 49152 + st * 16384;
#pragma unroll
        for (int ks = 0; ks < 4; ks++) {
            uint32_t ah[2][4];
            const int u = ks * 2 + ((lane >> 4) & 1);
#pragma unroll
            for (int mt = 0; mt < 2; mt++) {
                int row = wm * 32 + mt * 16 + (lane & 15);
                ldmx4(ah[mt], ab + row * 128 + ((u ^ (row & 7)) << 4));
            }
            const int brow = (lane & 7) + ((lane & 16) ? 8 : 0);
            const int bu = ks * 2 + ((lane >> 3) & 1);
#pragma unroll
            for (int p = 0; p < 4; p++) {
                int nl = wn * 64 + p * 16 + brow;   // local col in [0,128)
                uint32_t bh[4];
                ldmx4(bh, bb + nl * 128 + ((bu ^ (nl & 7)) << 4));
#pragma unroll
                for (int mt = 0; mt < 2; mt++) {
                    mma16816(d[mt][2 * p + 0], ah[mt], &bh[0]);
                    mma16816(d[mt][2 * p + 1], ah[mt], &bh[2]);
                }
            }
        }
    }

    // epilogue: direct global stores (fp32 out, or fp16 for conv1 -> g_C)
#pragma unroll
    for (int mt = 0; mt < 2; mt++) {
        int r0 = mbase + wm * 32 + mt * 16 + lane / 4;
#pragma unroll
        for (int t = 0; t < 8; t++) {
            int gc = n0 + wn * 64 + t * 8 + (lane % 4) * 2;
            float bx = bias[gc], by = bias[gc + 1];
            if (FUSE_SKIP) { bx += bias2[gc]; by += bias2[gc + 1]; }
            if (OUT_HALF) {
                fh* oh = (fh*)outv;
                if (r0 < M) {
                    __half2 v = __floats2half2_rn(d[mt][t][0] + bx, d[mt][t][1] + by);
                    *(__half2*)(oh + (size_t)r0 * 256 + gc) = v;
                }
                if (r0 + 8 < M) {
                    __half2 v = __floats2half2_rn(d[mt][t][2] + bx, d[mt][t][3] + by);
                    *(__half2*)(oh + (size_t)(r0 + 8) * 256 + gc) = v;
                }
            } else {
                float* of = (float*)outv;
                if (r0 < M) {
                    float2 v = {d[mt][t][0] + bx, d[mt][t][1] + by};
                    *(float2*)(of + (size_t)r0 * 256 + gc) = v;
                }
                if (r0 + 8 < M) {
                    float2 v = {d[mt][t][2] + bx, d[mt][t][3] + by};
                    *(float2*)(of + (size_t)(r0 + 8) * 256 + gc) = v;
                }
            }
        }
    }
}

// ---------------- PDL launcher ----------------
static void launch_pdl(const void* fn, dim3 grid, dim3 block, size_t smem, void** args) {
    cudaLaunchConfig_t cfg = {};
    cfg.gridDim = grid;
    cfg.blockDim = block;
    cfg.dynamicSmemBytes = smem;
    cfg.stream = 0;
    cudaLaunchAttribute at[1];
    at[0].id = cudaLaunchAttributeProgrammaticStreamSerialization;
    at[0].val.programmaticStreamSerializationAllowed = 1;
    cfg.attrs = at;
    cfg.numAttrs = 1;
    cudaLaunchKernelExC(&cfg, fn, args);
}

// ---------------- launch ----------------
extern "C" void kernel_launch(void* const* d_in, const int* in_sizes, int n_in,
                              void* d_out, int out_size) {
    const float* feats = (const float*)d_in[0];
    const float* gn1_w = (const float*)d_in[1];
    const float* gn1_b = (const float*)d_in[2];
    const float* W1    = (const float*)d_in[3];
    const float* b1    = (const float*)d_in[4];
    const float* gn2_w = (const float*)d_in[5];
    const float* gn2_b = (const float*)d_in[6];
    const float* W2    = (const float*)d_in[7];
    const float* b2    = (const float*)d_in[8];
    const float* Wskip = (const float*)d_in[9];
    const float* bskip = (const float*)d_in[10];
    const int* pool_seg = (const int*)d_in[11];
    const int* nbr_idx  = (const int*)d_in[12];
    float* out = (float*)d_out;

    int N = in_sizes[0] / 128;
    int M = in_sizes[12] / 27;

    float *A, *B, *cnt, *part;
    cudaGetSymbolAddress((void**)&A, g_A);
    cudaGetSymbolAddress((void**)&B, g_B);
    cudaGetSymbolAddress((void**)&cnt, g_cnt);
    cudaGetSymbolAddress((void**)&part, g_part);
    fh *C, *hd, *xd, *h2, *W1p, *W2p, *WSp;
    cudaGetSymbolAddress((void**)&C, g_C);
    cudaGetSymbolAddress((void**)&hd, g_hd);
    cudaGetSymbolAddress((void**)&xd, g_xd);
    cudaGetSymbolAddress((void**)&h2, g_h2);
    cudaGetSymbolAddress((void**)&W1p, g_W1);
    cudaGetSymbolAddress((void**)&W2p, g_W2);
    cudaGetSymbolAddress((void**)&WSp, g_WS);

    cudaFuncSetAttribute(conv_hmma<128, false, true>,
                         cudaFuncAttributeMaxDynamicSharedMemorySize, CONV_SMEM);
    cudaFuncSetAttribute(conv_hmma<256, true, false>,
                         cudaFuncAttributeMaxDynamicSharedMemorySize, CONV_SMEM);

    // zero atomic accumulators (normal launch: chain head)
    {
        size_t n128 = (size_t)M * 128;
        void* a[] = {&A, &B, &cnt, &n128, (void*)&M};
        launch_pdl((const void*)zero_all, dim3(4096), dim3(256), 0, a);
    }
    // weights prep (single kernel)
    {
        void* a[] = {(void*)&W1, (void*)&W2, (void*)&Wskip};
        launch_pdl((const void*)prep_all, dim3(3072), dim3(256), 0, a);
    }
    // GN1 stats + finalize
    {
        void* a[] = {(void*)&feats, &N, &part};
        launch_pdl((const void*)gn_stats<128>, dim3(NB), dim3(256), 0, a);
    }
    {
        float rc = 1.f / ((float)N * 4.f);
        void* a[] = {&part, (void*)&gn1_w, (void*)&gn1_b, &rc};
        launch_pdl((const void*)gn_finalize<128, 4>, dim3(1), dim3(128), 0, a);
    }
    // GN1 apply + SiLU + segment sums (vector red); then means -> fp16 planes
    {
        long dthreads = (long)N * 32;
        int g = (int)((dthreads + 255) / 256);
        void* a[] = {(void*)&feats, (void*)&pool_seg, &N};
        launch_pdl((const void*)downsample_kernel, dim3(g), dim3(256), 0, a);
    }
    {
        long fthreads = (long)M * 32;
        int g = (int)((fthreads + 255) / 256);
        void* a[] = {(void*)&M};
        launch_pdl((const void*)finalize_down, dim3(g), dim3(256), 0, a);
    }

    int nconv = ((M + 127) / 128) * 2;   // x2 N-halves
    const fh* nullfh = nullptr;
    const float* nullf = nullptr;

    // conv1: h1 = conv(h_d, W1) + b1 (fp16 out)
    {
        void* outp = (void*)C;
        void* a[] = {&hd, &W1p, (void*)&nullfh, (void*)&nullfh,
                     (void*)&b1, (void*)&nullf, (void*)&nbr_idx, &outp, &M};
        launch_pdl((const void*)conv_hmma<128, false, true>,
                   dim3(nconv), dim3(256), CONV_SMEM, a);
    }
    // GN2 stats (fp16 input) + finalize + apply
    {
        void* a[] = {&C, &M, &part};
        launch_pdl((const void*)gn_stats_h<256>, dim3(NB), dim3(256), 0, a);
    }
    {
        float rc = 1.f / ((float)M * 8.f);
        void* a[] = {&part, (void*)&gn2_w, (void*)&gn2_b, &rc};
        launch_pdl((const void*)gn_finalize<256, 8>, dim3(1), dim3(256), 0, a);
    }
    {
        long athreads = (long)M * 64;
        int g = (int)((athreads + 255) / 256);
        void* a[] = {(void*)&M};
        launch_pdl((const void*)apply_gn2, dim3(g), dim3(256), 0, a);
    }
    // conv2 + fused skip: out = conv(h2, W2) + b2 + x_d @ Wskip + bskip
    {
        void* outp = (void*)out;
        void* a[] = {&h2, &W2p, &xd, &WSp,
                     (void*)&b2, (void*)&bskip, (void*)&nbr_idx, &outp, &M};
        launch_pdl((const void*)conv_hmma<256, true, false>,
                   dim3(nconv), dim3(256), CONV_SMEM, a);
    }
}

// round 15
// speedup vs baseline: 1.3748x; 1.0101x over previous
#include <cuda_runtime.h>
#include <cuda_bf16.h>
#include <cuda_fp16.h>
#include <cstdint>

#define MMAX 200704
#define NB 512

typedef __half fh;

// ---------------- scratch (device globals; no allocation allowed) ----------------
__device__ float g_A[(size_t)MMAX * 128];   // h segment-sum accumulator
__device__ float g_B[(size_t)MMAX * 128];   // x segment-sum accumulator
__device__ fh    g_C[(size_t)MMAX * 256];   // h1 (conv1 out, fp16)
__device__ float g_cnt[MMAX];
__device__ float g_part[2 * NB * 256];
__device__ float g_scale[256];
__device__ float g_shift[256];
__device__ __align__(16) fh g_zrow[64];     // safe src for zero-fill cp.async
// fp16 operand planes (single plane each)
__device__ fh g_hd[(size_t)MMAX * 128];
__device__ fh g_xd[(size_t)MMAX * 128];
__device__ fh g_h2[(size_t)MMAX * 256];
// weights: chunked+pre-swizzled layout [tap*NCH2+ch][n=256][64] (fp16, 32KB blocks,
// 128B rows with slot swizzle q^(n&7))
__device__ __align__(16) fh g_W1[27 * 256 * 128];
__device__ __align__(16) fh g_W2[27 * 256 * 256];
__device__ __align__(16) fh g_WS[256 * 128];

__device__ __forceinline__ float silu_f(float x) { return x / (1.f + __expf(-x)); }

// PDL: wait for previous grid's implicit completion trigger (acquire semantics)
__device__ __forceinline__ void gdc_wait() {
    asm volatile("griddepcontrol.wait;" ::: "memory");
}

__device__ __forceinline__ uint32_t smem_u32(const void* p) {
    uint32_t a;
    asm("{ .reg .u64 t; cvta.to.shared.u64 t, %1; cvt.u32.u64 %0, t; }" : "=r"(a) : "l"(p));
    return a;
}
// zero-fill form: src-size=0 -> writes 16 zero bytes, NO global read issued
__device__ __forceinline__ void cp_async16z(uint32_t dst, const void* src, uint32_t srcsz) {
    asm volatile("cp.async.cg.shared.global [%0], [%1], 16, %2;"
                 :: "r"(dst), "l"(src), "r"(srcsz));
}
__device__ __forceinline__ void cp_commit() {
    asm volatile("cp.async.commit_group;" ::: "memory");
}
__device__ __forceinline__ void cp_wait0() { asm volatile("cp.async.wait_group 0;" ::: "memory"); }
__device__ __forceinline__ void cp_wait1() { asm volatile("cp.async.wait_group 1;" ::: "memory"); }
// bulk g2s copy completing on an mbarrier (sm_90 base feature)
__device__ __forceinline__ void cp_bulk_g2s(uint32_t dst, const void* src, uint32_t bytes,
                                            uint32_t mbar) {
    asm volatile(
        "cp.async.bulk.shared::cta.global.mbarrier::complete_tx::bytes [%0], [%1], %2, [%3];"
        :: "r"(dst), "l"(src), "r"(bytes), "r"(mbar) : "memory");
}
// vector reduction: 4 floats, one red op (sm_90+, PTX ISA 8.1)
__device__ __forceinline__ void red_add_v4(float* addr, float4 v) {
    asm volatile("red.global.add.v4.f32 [%0], {%1, %2, %3, %4};"
                 :: "l"(addr), "f"(v.x), "f"(v.y), "f"(v.z), "f"(v.w) : "memory");
}
#define MBARRIER_INIT(addr, cnt) \
    asm volatile("mbarrier.init.shared.b64 [%0], %1;" :: "r"(addr), "r"(cnt) : "memory")
#define MBAR_ARRIVE_EXPECT(m, b) \
    asm volatile("mbarrier.arrive.expect_tx.shared.b64 _, [%0], %1;" :: "r"(m), "r"(b) : "memory")
#define MBARRIER_WAIT_PARITY(addr, par) do {                                           \
    uint32_t _m = (addr); uint32_t _p = (par); uint32_t _done;                         \
    asm volatile("{\n\t.reg .pred p;\n\t"                                              \
        "mbarrier.try_wait.parity.acquire.cta.shared::cta.b64 p, [%1], %2;\n\t"        \
        "selp.b32 %0, 1, 0, p;\n\t}" : "=r"(_done) : "r"(_m), "r"(_p) : "memory");     \
    if (!_done) {                                                                      \
        asm volatile("{\n\t.reg .pred P1;\n\tWL_%=:\n\t"                               \
            "mbarrier.try_wait.parity.acquire.cta.shared::cta.b64 P1, [%0], %1, 0x989680;\n\t" \
            "@P1 bra.uni WD_%=;\n\tbra.uni WL_%=;\n\tWD_%=:\n\t}"                      \
            :: "r"(_m), "r"(_p) : "memory");                                           \
    } } while (0)
#define FENCE_ASYNC() asm volatile("fence.proxy.async.shared::cta;" ::: "memory")

__device__ __forceinline__ void ldmx4(uint32_t* r, uint32_t addr) {
    asm volatile("ldmatrix.sync.aligned.m8n8.x4.shared.b16 {%0,%1,%2,%3}, [%4];"
                 : "=r"(r[0]), "=r"(r[1]), "=r"(r[2]), "=r"(r[3]) : "r"(addr));
}
__device__ __forceinline__ void mma16816(float* d, const uint32_t* a, const uint32_t* b) {
    asm volatile(
        "mma.sync.aligned.m16n8k16.row.col.f32.f16.f16.f32 "
        "{%0,%1,%2,%3}, {%4,%5,%6,%7}, {%8,%9}, {%0,%1,%2,%3};"
        : "+f"(d[0]), "+f"(d[1]), "+f"(d[2]), "+f"(d[3])
        : "r"(a[0]), "r"(a[1]), "r"(a[2]), "r"(a[3]), "r"(b[0]), "r"(b[1]));
}

// ---------------- small kernels ----------------
// one launch zeroes g_A, g_B (M*128 each) and g_cnt (M)
__global__ void zero_all(float* a, float* b, float* cnt, size_t n128, int M) {
    size_t i = (size_t)blockIdx.x * blockDim.x + threadIdx.x;
    size_t s = (size_t)gridDim.x * blockDim.x;
    for (size_t j = i; j < n128; j += s) { a[j] = 0.f; b[j] = 0.f; }
    for (size_t j = i; j < (size_t)M; j += s) cnt[j] = 0.f;
}

// single prep kernel: transpose + fp16 + chunk/swizzle all three weight tensors.
__global__ void prep_all(const float* __restrict__ W1, const float* __restrict__ W2,
                         const float* __restrict__ WS) {
    const int T1 = 27 * 256 * 128;
    const int T2 = 27 * 256 * 256;
    const int T3 = 256 * 128;
    const int total = T1 + T2 + T3;
    int idx = blockIdx.x * blockDim.x + threadIdx.x;
    int stride = gridDim.x * blockDim.x;
    for (; idx < total; idx += stride) {
        const float* W;
        fh* wo;
        int rem, cin;
        if (idx < T1) { W = W1; wo = g_W1; rem = idx; cin = 128; }
        else if (idx < T1 + T2) { W = W2; wo = g_W2; rem = idx - T1; cin = 256; }
        else { W = WS; wo = g_WS; rem = idx - T1 - T2; cin = 128; }
        int c = rem % cin;
        int n = (rem / cin) % 256;
        int k = rem / (cin * 256);
        float v = W[((size_t)k * cin + c) * 256 + n];
        int NCH2 = cin / 64;
        int ch = c >> 6, kq = (c >> 3) & 7, o = c & 7;
        size_t dst = ((size_t)(k * NCH2 + ch) * 256 + n) * 64 + ((kq ^ (n & 7)) << 3) + o;
        wo[dst] = __float2half(v);
    }
}

template <int C>
__global__ void gn_stats(const float* __restrict__ x, int n, float* __restrict__ part) {
    gdc_wait();
    const int CG = C / 4;
    const int RPB = 256 / CG;
    int tid = threadIdx.x;
    int cg = tid % CG;
    int rsub = tid / CG;
    float4 s = {0, 0, 0, 0}, q = {0, 0, 0, 0};
    for (long r = (long)blockIdx.x * RPB + rsub; r < n; r += (long)gridDim.x * RPB) {
        float4 v = *(const float4*)(x + r * C + cg * 4);
        s.x += v.x; s.y += v.y; s.z += v.z; s.w += v.w;
        q.x += v.x * v.x; q.y += v.y * v.y; q.z += v.z * v.z; q.w += v.w * v.w;
    }
    __shared__ float4 sh[256], sq[256];
    sh[tid] = s; sq[tid] = q;
    __syncthreads();
    if (rsub == 0) {
        for (int j = 1; j < RPB; j++) {
            float4 t = sh[j * CG + cg];
            s.x += t.x; s.y += t.y; s.z += t.z; s.w += t.w;
            t = sq[j * CG + cg];
            q.x += t.x; q.y += t.y; q.z += t.z; q.w += t.w;
        }
        *(float4*)&part[blockIdx.x * C + cg * 4] = s;
        *(float4*)&part[NB * C + blockIdx.x * C + cg * 4] = q;
    }
}

// fp16-input GN stats (C=256)
template <int C>
__global__ void gn_stats_h(const fh* __restrict__ x, int n, float* __restrict__ part) {
    gdc_wait();
    const int CG = C / 4;
    const int RPB = 256 / CG;
    int tid = threadIdx.x;
    int cg = tid % CG;
    int rsub = tid / CG;
    float4 s = {0, 0, 0, 0}, q = {0, 0, 0, 0};
    for (long r = (long)blockIdx.x * RPB + rsub; r < n; r += (long)gridDim.x * RPB) {
        uint2 raw = *(const uint2*)(x + r * C + cg * 4);
        float2 v01 = __half22float2(*(__half2*)&raw.x);
        float2 v23 = __half22float2(*(__half2*)&raw.y);
        s.x += v01.x; s.y += v01.y; s.z += v23.x; s.w += v23.y;
        q.x += v01.x * v01.x; q.y += v01.y * v01.y;
        q.z += v23.x * v23.x; q.w += v23.y * v23.y;
    }
    __shared__ float4 sh[256], sq[256];
    sh[tid] = s; sq[tid] = q;
    __syncthreads();
    if (rsub == 0) {
        for (int j = 1; j < RPB; j++) {
            float4 t = sh[j * CG + cg];
            s.x += t.x; s.y += t.y; s.z += t.z; s.w += t.w;
            t = sq[j * CG + cg];
            q.x += t.x; q.y += t.y; q.z += t.z; q.w += t.w;
        }
        *(float4*)&part[blockIdx.x * C + cg * 4] = s;
        *(float4*)&part[NB * C + blockIdx.x * C + cg * 4] = q;
    }
}

// PARALLEL finalize: 1024 threads; thread (c, slice) sums NB/SL partial blocks,
// slice-reduce in smem, then group reduction. Replaces the 512-iteration serial
// walk (43.6us @ occ 6% in the R14 profile) with a 32-warp pipelined reduction.
template <int C, int CPG>
__global__ void gn_finalize(const float* __restrict__ part, const float* __restrict__ w,
                            const float* __restrict__ b, float rcount) {
    gdc_wait();
    const int SL = 1024 / C;               // 8 slices (C=128) or 4 (C=256)
    int tid = threadIdx.x;
    int c = tid % C;
    int sl = tid / C;
    float s = 0.f, q = 0.f;
#pragma unroll 4
    for (int blk = sl; blk < NB; blk += SL) {
        s += part[blk * C + c];
        q += part[NB * C + blk * C + c];
    }
    __shared__ float cs[1024], cq[1024];
    cs[tid] = s; cq[tid] = q;
    __syncthreads();
    if (sl == 0) {
        for (int j = 1; j < SL; j++) { s += cs[j * C + c]; q += cq[j * C + c]; }
        cs[c] = s; cq[c] = q;
    }
    __syncthreads();
    __shared__ float mu[32], rs[32];
    if (tid < C / CPG) {
        float S = 0.f, Q = 0.f;
        for (int j = 0; j < CPG; j++) { S += cs[tid * CPG + j]; Q += cq[tid * CPG + j]; }
        float m = S * rcount;
        float v = Q * rcount - m * m;
        mu[tid] = m;
        rs[tid] = rsqrtf(v + 1e-5f);
    }
    __syncthreads();
    if (tid < C) {
        int g = tid / CPG;
        float sc = w[tid] * rs[g];
        g_scale[tid] = sc;
        g_shift[tid] = b[tid] - mu[g] * sc;
    }
}

__global__ void downsample_kernel(const float* __restrict__ feats,
                                  const int* __restrict__ seg, int n) {
    long t = (long)blockIdx.x * blockDim.x + threadIdx.x;
    if (t >= (long)n * 32) { gdc_wait(); return; }
    int row = (int)(t >> 5);
    int q = (int)(t & 31);
    int c = q * 4;
    int s = seg[row];                                  // harness input: safe pre-wait
    float4 f = *(const float4*)(feats + (long)row * 128 + c);
    gdc_wait();                                        // g_scale/g_shift + zeroed bufs
    float4 sc = *(const float4*)(g_scale + c);
    float4 sh = *(const float4*)(g_shift + c);
    float4 h;
    h.x = silu_f(f.x * sc.x + sh.x);
    h.y = silu_f(f.y * sc.y + sh.y);
    h.z = silu_f(f.z * sc.z + sh.z);
    h.w = silu_f(f.w * sc.w + sh.w);
    red_add_v4(g_A + (long)s * 128 + c, h);
    red_add_v4(g_B + (long)s * 128 + c, f);
    if (q == 0) atomicAdd(g_cnt + s, 1.f);
}

__global__ void finalize_down(int M) {
    gdc_wait();
    long t = (long)blockIdx.x * blockDim.x + threadIdx.x;
    if (t >= (long)M * 32) return;
    int row = (int)(t >> 5);
    int c = (int)(t & 31) * 4;
    float ic = 1.f / fmaxf(g_cnt[row], 1.f);
    size_t base = (size_t)row * 128 + c;
    float4 va = *(const float4*)(g_A + base);
    float4 vb = *(const float4*)(g_B + base);
    g_hd[base + 0] = __float2half(va.x * ic);
    g_hd[base + 1] = __float2half(va.y * ic);
    g_hd[base + 2] = __float2half(va.z * ic);
    g_hd[base + 3] = __float2half(va.w * ic);
    g_xd[base + 0] = __float2half(vb.x * ic);
    g_xd[base + 1] = __float2half(vb.y * ic);
    g_xd[base + 2] = __float2half(vb.z * ic);
    g_xd[base + 3] = __float2half(vb.w * ic);
}

// GN2 apply + SiLU: fp16 h1 -> fp16 h2
__global__ void apply_gn2(int M) {
    gdc_wait();
    long t = (long)blockIdx.x * blockDim.x + threadIdx.x;
    if (t >= (long)M * 64) return;
    int row = (int)(t >> 6);
    int c = (int)(t & 63) * 4;
    size_t base = (size_t)row * 256 + c;
    uint2 raw = *(const uint2*)(g_C + base);
    float2 v01 = __half22float2(*(__half2*)&raw.x);
    float2 v23 = __half22float2(*(__half2*)&raw.y);
    float4 sc = *(const float4*)(g_scale + c);
    float4 sh = *(const float4*)(g_shift + c);
    __half2 o01 = __floats2half2_rn(silu_f(v01.x * sc.x + sh.x),
                                    silu_f(v01.y * sc.y + sh.y));
    __half2 o23 = __floats2half2_rn(silu_f(v23.x * sc.z + sh.z),
                                    silu_f(v23.y * sc.w + sh.w));
    uint2 o;
    o.x = *(uint32_t*)&o01;
    o.y = *(uint32_t*)&o23;
    *(uint2*)(g_h2 + base) = o;
}

// ---------------- HMMA gather-conv: fp16, tile 128x128, K=64 chunks, occ 2 ------
// (unchanged from R13/R14 -- calibrated state)
static constexpr int CONV_SMEM = 98336 + 28 * 128 * 4;

template <int CIN, bool FUSE_SKIP, bool OUT_HALF>
__global__ __launch_bounds__(256, 2) void conv_hmma(
    const fh* __restrict__ x, const fh* __restrict__ w,
    const fh* __restrict__ sx, const fh* __restrict__ sw,
    const float* __restrict__ bias, const float* __restrict__ bias2,
    const int* __restrict__ nbr, void* __restrict__ outv, int M) {
    extern __shared__ char smem[];
    constexpr int NCH2 = CIN / 64;
    constexpr int NREG = 27 * NCH2;
    constexpr int TC = NREG + (FUSE_SKIP ? 2 : 0);
    constexpr int NT = FUSE_SKIP ? 28 : 27;
    const uint32_t sbase = smem_u32(smem);
    const uint32_t mbars = sbase + 98304;
    int* nid = (int*)(smem + 98336);
    const int tid = threadIdx.x;
    const int mbase = (blockIdx.x >> 1) * 128;
    const int n0 = (blockIdx.x & 1) * 128;
    const int lane = tid & 31;
    const int wm = (tid >> 5) >> 1;   // 0..3
    const int wn = (tid >> 5) & 1;    // 0..1

    // prologue independent of predecessor output (nbr is a harness input)
    if (tid == 0) {
        MBARRIER_INIT(mbars + 0, 1);
        MBARRIER_INIT(mbars + 8, 1);
        MBARRIER_INIT(mbars + 16, 1);
    }
    for (int u = tid; u < NT * 128; u += 256) {
        int tap = u >> 7;
        int r = mbase + (u & 127);
        nid[u] = (tap == 27) ? ((r < M) ? r : -1)
                             : ((r < M) ? nbr[(size_t)r * 27 + tap] : -1);
    }
    __syncthreads();
    gdc_wait();   // operands (planes/weights) produced by predecessor grids

    float d[2][8][4];
#pragma unroll
    for (int a = 0; a < 2; a++)
#pragma unroll
        for (int b = 0; b < 8; b++)
#pragma unroll
            for (int c = 0; c < 4; c++) d[a][b][c] = 0.f;

    auto issueC = [&](int i) {
        int tap, c0, cin, ch;
        const fh *ax, *bw;
        if (i < NREG) {
            tap = i / NCH2; ch = i % NCH2; c0 = ch * 64; cin = CIN;
            ax = x;
            bw = w + (size_t)(tap * NCH2 + ch) * 16384 + n0 * 64;
        } else {
            tap = 27; ch = i - NREG; c0 = ch * 64; cin = 128;
            ax = sx;
            bw = sw + (size_t)ch * 16384 + n0 * 64;
        }
        const int* nt = nid + tap * 128;
        int st = i % 3;
        const uint32_t ab = sbase + st * 16384;
        const uint32_t bb = sbase + 49152 + st * 16384;
        if (tid == 0) {
            FENCE_ASYNC();
            MBAR_ARRIVE_EXPECT(mbars + st * 8, 16384u);
            cp_bulk_g2s(bb, bw, 16384u, mbars + st * 8);
        }
#pragma unroll
        for (int wv = 0; wv < 4; wv++) {
            int u = tid + wv * 256;
            int r = u >> 3, q = u & 7;
            int src = nt[r];
            const fh* sp = (src >= 0) ? (ax + (size_t)src * cin + c0 + q * 8)
                                      : (const fh*)g_zrow;
            cp_async16z(ab + r * 128 + ((q ^ (r & 7)) << 4),
                        sp, (src >= 0) ? 16u : 0u);
        }
        cp_commit();
    };

    issueC(0);
    if (TC > 1) issueC(1);

    for (int i = 0; i < TC; i++) {
        if (i < TC - 1) cp_wait1();
        else cp_wait0();
        int st = i % 3;
        MBARRIER_WAIT_PARITY(mbars + st * 8, (i / 3) & 1);
        __syncthreads();
        if (i + 2 < TC) issueC(i + 2);   // writes buf (i-1)%3: drained by sync

        const uint32_t ab = sbase + st * 16384;
        const uint32_t bb = sbase + 49152 + st * 16384;
#pragma unroll
        for (int ks = 0; ks < 4; ks++) {
            uint32_t ah[2][4];
            const int u = ks * 2 + ((lane >> 4) & 1);
#pragma unroll
            for (int mt = 0; mt < 2; mt++) {
                int row = wm * 32 + mt * 16 + (lane & 15);
                ldmx4(ah[mt], ab + row * 128 + ((u ^ (row & 7)) << 4));
            }
            const int brow = (lane & 7) + ((lane & 16) ? 8 : 0);
            const int bu = ks * 2 + ((lane >> 3) & 1);
#pragma unroll
            for (int p = 0; p < 4; p++) {
                int nl = wn * 64 + p * 16 + brow;   // local col in [0,128)
                uint32_t bh[4];
                ldmx4(bh, bb + nl * 128 + ((bu ^ (nl & 7)) << 4));
#pragma unroll
                for (int mt = 0; mt < 2; mt++) {
                    mma16816(d[mt][2 * p + 0], ah[mt], &bh[0]);
                    mma16816(d[mt][2 * p + 1], ah[mt], &bh[2]);
                }
            }
        }
    }

    // epilogue: direct global stores (fp32 out, or fp16 for conv1 -> g_C)
#pragma unroll
    for (int mt = 0; mt < 2; mt++) {
        int r0 = mbase + wm * 32 + mt * 16 + lane / 4;
#pragma unroll
        for (int t = 0; t < 8; t++) {
            int gc = n0 + wn * 64 + t * 8 + (lane % 4) * 2;
            float bx = bias[gc], by = bias[gc + 1];
            if (FUSE_SKIP) { bx += bias2[gc]; by += bias2[gc + 1]; }
            if (OUT_HALF) {
                fh* oh = (fh*)outv;
                if (r0 < M) {
                    __half2 v = __floats2half2_rn(d[mt][t][0] + bx, d[mt][t][1] + by);
                    *(__half2*)(oh + (size_t)r0 * 256 + gc) = v;
                }
                if (r0 + 8 < M) {
                    __half2 v = __floats2half2_rn(d[mt][t][2] + bx, d[mt][t][3] + by);
                    *(__half2*)(oh + (size_t)(r0 + 8) * 256 + gc) = v;
                }
            } else {
                float* of = (float*)outv;
                if (r0 < M) {
                    float2 v = {d[mt][t][0] + bx, d[mt][t][1] + by};
                    *(float2*)(of + (size_t)r0 * 256 + gc) = v;
                }
                if (r0 + 8 < M) {
                    float2 v = {d[mt][t][2] + bx, d[mt][t][3] + by};
                    *(float2*)(of + (size_t)(r0 + 8) * 256 + gc) = v;
                }
            }
        }
    }
}

// ---------------- PDL launcher ----------------
static void launch_pdl(const void* fn, dim3 grid, dim3 block, size_t smem, void** args) {
    cudaLaunchConfig_t cfg = {};
    cfg.gridDim = grid;
    cfg.blockDim = block;
    cfg.dynamicSmemBytes = smem;
    cfg.stream = 0;
    cudaLaunchAttribute at[1];
    at[0].id = cudaLaunchAttributeProgrammaticStreamSerialization;
    at[0].val.programmaticStreamSerializationAllowed = 1;
    cfg.attrs = at;
    cfg.numAttrs = 1;
    cudaLaunchKernelExC(&cfg, fn, args);
}

// ---------------- launch ----------------
extern "C" void kernel_launch(void* const* d_in, const int* in_sizes, int n_in,
                              void* d_out, int out_size) {
    const float* feats = (const float*)d_in[0];
    const float* gn1_w = (const float*)d_in[1];
    const float* gn1_b = (const float*)d_in[2];
    const float* W1    = (const float*)d_in[3];
    const float* b1    = (const float*)d_in[4];
    const float* gn2_w = (const float*)d_in[5];
    const float* gn2_b = (const float*)d_in[6];
    const float* W2    = (const float*)d_in[7];
    const float* b2    = (const float*)d_in[8];
    const float* Wskip = (const float*)d_in[9];
    const float* bskip = (const float*)d_in[10];
    const int* pool_seg = (const int*)d_in[11];
    const int* nbr_idx  = (const int*)d_in[12];
    float* out = (float*)d_out;

    int N = in_sizes[0] / 128;
    int M = in_sizes[12] / 27;

    float *A, *B, *cnt, *part;
    cudaGetSymbolAddress((void**)&A, g_A);
    cudaGetSymbolAddress((void**)&B, g_B);
    cudaGetSymbolAddress((void**)&cnt, g_cnt);
    cudaGetSymbolAddress((void**)&part, g_part);
    fh *C, *hd, *xd, *h2, *W1p, *W2p, *WSp;
    cudaGetSymbolAddress((void**)&C, g_C);
    cudaGetSymbolAddress((void**)&hd, g_hd);
    cudaGetSymbolAddress((void**)&xd, g_xd);
    cudaGetSymbolAddress((void**)&h2, g_h2);
    cudaGetSymbolAddress((void**)&W1p, g_W1);
    cudaGetSymbolAddress((void**)&W2p, g_W2);
    cudaGetSymbolAddress((void**)&WSp, g_WS);

    cudaFuncSetAttribute(conv_hmma<128, false, true>,
                         cudaFuncAttributeMaxDynamicSharedMemorySize, CONV_SMEM);
    cudaFuncSetAttribute(conv_hmma<256, true, false>,
                         cudaFuncAttributeMaxDynamicSharedMemorySize, CONV_SMEM);

    // zero atomic accumulators (chain head)
    {
        size_t n128 = (size_t)M * 128;
        void* a[] = {&A, &B, &cnt, &n128, (void*)&M};
        launch_pdl((const void*)zero_all, dim3(4096), dim3(256), 0, a);
    }
    // weights prep (single kernel)
    {
        void* a[] = {(void*)&W1, (void*)&W2, (void*)&Wskip};
        launch_pdl((const void*)prep_all, dim3(3072), dim3(256), 0, a);
    }
    // GN1 stats + finalize (parallel finalize, 1024 threads)
    {
        void* a[] = {(void*)&feats, &N, &part};
        launch_pdl((const void*)gn_stats<128>, dim3(NB), dim3(256), 0, a);
    }
    {
        float rc = 1.f / ((float)N * 4.f);
        void* a[] = {&part, (void*)&gn1_w, (void*)&gn1_b, &rc};
        launch_pdl((const void*)gn_finalize<128, 4>, dim3(1), dim3(1024), 0, a);
    }
    // GN1 apply + SiLU + segment sums (vector red); then means -> fp16 planes
    {
        long dthreads = (long)N * 32;
        int g = (int)((dthreads + 255) / 256);
        void* a[] = {(void*)&feats, (void*)&pool_seg, &N};
        launch_pdl((const void*)downsample_kernel, dim3(g), dim3(256), 0, a);
    }
    {
        long fthreads = (long)M * 32;
        int g = (int)((fthreads + 255) / 256);
        void* a[] = {(void*)&M};
        launch_pdl((const void*)finalize_down, dim3(g), dim3(256), 0, a);
    }

    int nconv = ((M + 127) / 128) * 2;   // x2 N-halves
    const fh* nullfh = nullptr;
    const float* nullf = nullptr;

    // conv1: h1 = conv(h_d, W1) + b1 (fp16 out)
    {
        void* outp = (void*)C;
        void* a[] = {&hd, &W1p, (void*)&nullfh, (void*)&nullfh,
                     (void*)&b1, (void*)&nullf, (void*)&nbr_idx, &outp, &M};
        launch_pdl((const void*)conv_hmma<128, false, true>,
                   dim3(nconv), dim3(256), CONV_SMEM, a);
    }
    // GN2 stats (fp16 input) + finalize + apply
    {
        void* a[] = {&C, &M, &part};
        launch_pdl((const void*)gn_stats_h<256>, dim3(NB), dim3(256), 0, a);
    }
    {
        float rc = 1.f / ((float)M * 8.f);
        void* a[] = {&part, (void*)&gn2_w, (void*)&gn2_b, &rc};
        launch_pdl((const void*)gn_finalize<256, 8>, dim3(1), dim3(1024), 0, a);
    }
    {
        long athreads = (long)M * 64;
        int g = (int)((athreads + 255) / 256);
        void* a[] = {(void*)&M};
        launch_pdl((const void*)apply_gn2, dim3(g), dim3(256), 0, a);
    }
    // conv2 + fused skip: out = conv(h2, W2) + b2 + x_d @ Wskip + bskip
    {
        void* outp = (void*)out;
        void* a[] = {&h2, &W2p, &xd, &WSp,
                     (void*)&b2, (void*)&bskip, (void*)&nbr_idx, &outp, &M};
        launch_pdl((const void*)conv_hmma<256, true, false>,
                   dim3(nconv), dim3(256), CONV_SMEM, a);
    }
}